// round 6
// baseline (speedup 1.0000x reference)
#include <cuda_runtime.h>
#include <cuda_bf16.h>
#include <math.h>

typedef unsigned int u32;
typedef unsigned long long u64;
typedef unsigned char u8;
typedef unsigned short u16;
typedef __nv_bfloat16 bf16;

#define B_   8
#define S_   2048
#define D_   1024
#define DFF_ 4096
#define M_   (B_*S_)

// ---------------- scratch (device globals) ----------------
// Each operand: bf16 hi + e4m3(v*m) + e4m3((v-hi)*256*m)
__device__ bf16 g_xh[(size_t)M_*D_];    __device__ u8 g_x8[(size_t)M_*D_],  g_xl[(size_t)M_*D_];
__device__ bf16 g_Wqh[(size_t)D_*D_];   __device__ u8 g_Wq8[(size_t)D_*D_], g_Wql[(size_t)D_*D_];
__device__ bf16 g_Wkh[(size_t)D_*D_];   __device__ u8 g_Wk8[(size_t)D_*D_], g_Wkl[(size_t)D_*D_];
__device__ bf16 g_Wvh[(size_t)D_*D_];   __device__ u8 g_Wv8[(size_t)D_*D_], g_Wvl[(size_t)D_*D_];
__device__ bf16 g_W1h[(size_t)DFF_*D_]; __device__ u8 g_W18[(size_t)DFF_*D_], g_W1l[(size_t)DFF_*D_];
__device__ bf16 g_W2h[(size_t)D_*DFF_]; __device__ u8 g_W28[(size_t)D_*DFF_], g_W2l[(size_t)D_*DFF_];
__device__ bf16 g_qh[(size_t)M_*D_];    __device__ u8 g_q8[(size_t)M_*D_],  g_ql[(size_t)M_*D_];
__device__ bf16 g_kh[(size_t)M_*D_];    __device__ u8 g_k8[(size_t)M_*D_],  g_kl[(size_t)M_*D_];
__device__ float g_v[(size_t)M_*D_];
__device__ bf16 g_vth[(size_t)B_*D_*S_]; __device__ u8 g_vt8[(size_t)B_*D_*S_], g_vtl[(size_t)B_*D_*S_];
__device__ float g_sc[(size_t)B_*S_*S_];
__device__ bf16 g_Ph[(size_t)B_*S_*S_]; __device__ u8 g_P8[(size_t)B_*S_*S_], g_Pl[(size_t)B_*S_*S_];
__device__ bf16 g_aoh[(size_t)M_*D_];   __device__ u8 g_ao8[(size_t)M_*D_], g_aol[(size_t)M_*D_];
__device__ bf16 g_hh[(size_t)M_*DFF_];  __device__ u8 g_h8[(size_t)M_*DFF_], g_hl[(size_t)M_*DFF_];

// ---------------- helpers ----------------
__device__ __forceinline__ u32 smem_u32(const void* p){
    u32 a;
    asm("{ .reg .u64 t; cvta.to.shared.u64 t, %1; cvt.u32.u64 %0, t; }" : "=r"(a) : "l"(p));
    return a;
}
__device__ __forceinline__ u32 pk(bf16 a, bf16 b){
    u16 ua = *(u16*)&a, ub = *(u16*)&b;
    return (u32)ua | ((u32)ub << 16);
}
// pack 2 fp32 -> e4m3x2 (16-bit result; low byte = v0, high byte = v1)
__device__ __forceinline__ u16 pk8(float v0, float v1){
    u16 r;
    asm("cvt.rn.satfinite.e4m3x2.f32 %0, %1, %2;" : "=h"(r) : "f"(v1), "f"(v0));
    return r;
}
// 16B-chunk XOR swizzle on 64B-row tiles (4 chunks/row)
__device__ __forceinline__ u32 swz(int row, int ch){
    return (u32)((row*4 + (ch ^ ((row>>1)&3))) * 16);
}

#define CP16(dst, src) asm volatile("cp.async.ca.shared.global [%0], [%1], 16;" :: "r"(dst), "l"(src) : "memory")
#define CP_COMMIT()    asm volatile("cp.async.commit_group;" ::: "memory")
#define CP_WAIT2()     asm volatile("cp.async.wait_group 2;" ::: "memory")
#define CP_WAIT1()     asm volatile("cp.async.wait_group 1;" ::: "memory")
#define CP_WAIT0()     asm volatile("cp.async.wait_group 0;" ::: "memory")

#define LDSM4(r, addr) asm volatile( \
    "ldmatrix.sync.aligned.m8n8.x4.shared.b16 {%0,%1,%2,%3}, [%4];" \
    : "=r"((r)[0]),"=r"((r)[1]),"=r"((r)[2]),"=r"((r)[3]) : "r"(addr))

#define MMA(c, a, b0, b1) asm volatile( \
    "mma.sync.aligned.m16n8k16.row.col.f32.bf16.bf16.f32 " \
    "{%0,%1,%2,%3},{%4,%5,%6,%7},{%8,%9},{%0,%1,%2,%3};" \
    : "+f"((c)[0]),"+f"((c)[1]),"+f"((c)[2]),"+f"((c)[3]) \
    : "r"((a)[0]),"r"((a)[1]),"r"((a)[2]),"r"((a)[3]),"r"(b0),"r"(b1))

#define MMA8(c, a, b0, b1) asm volatile( \
    "mma.sync.aligned.m16n8k32.row.col.f32.e4m3.e4m3.f32 " \
    "{%0,%1,%2,%3},{%4,%5,%6,%7},{%8,%9},{%0,%1,%2,%3};" \
    : "+f"((c)[0]),"+f"((c)[1]),"+f"((c)[2]),"+f"((c)[3]) \
    : "r"((a)[0]),"r"((a)[1]),"r"((a)[2]),"r"((a)[3]),"r"(b0),"r"(b1))

#define TILE8  8192        // 128 rows x 64 B
#define STG_B  32768       // 4 fp8 tiles (corr) or 2 bf16 tiles (main, first 16KB)
#define SMEM_SZ (3*STG_B)  // 98304, 3-stage ring

// ================= bf16-hi + fp8-correction tensor-core GEMM =================
// C = act( scale * (Ah@Bh^T + fcorr*(Al8@B8^T + A8@Bl8^T)) + bias )
// causal: 0 none, 1 skip bn>bm, 2 K bounded at (bm+1)*128
__global__ __launch_bounds__(256, 2) void gemm_mma(
    const bf16* __restrict__ Ah, const u8* __restrict__ A8, const u8* __restrict__ Al8,
    const bf16* __restrict__ Bh, const u8* __restrict__ B8, const u8* __restrict__ Bl8,
    const float* __restrict__ bias,
    float* __restrict__ C, bf16* __restrict__ Ch, u8* __restrict__ C8, u8* __restrict__ Cl8,
    int N, int K, long sA, long sB, long sC,
    float scale, float fcorr, float outm, int gelu, int causal)
{
    extern __shared__ char smem[];
    const int bm = blockIdx.y, bn = blockIdx.x, bz = blockIdx.z;
    if (causal == 1 && bn > bm) return;

    const int tid = threadIdx.x, lane = tid & 31, warp = tid >> 5;
    const int wm = warp >> 2, wn = warp & 3;   // 2x4 warps, 64m x 32n each
    const u32 sb = smem_u32(smem);

    const size_t aoff = (size_t)bz*sA + (size_t)bm*128*K;
    const size_t boff = (size_t)bz*sB + (size_t)bn*128*K;
    const bf16* Ah_b = Ah + aoff;  const u8* A8_b = A8 + aoff;  const u8* Al_b = Al8 + aoff;
    const bf16* Bh_b = Bh + boff;  const u8* B8_b = B8 + boff;  const u8* Bl_b = Bl8 + boff;

    const int Keff = (causal == 2) ? (bm + 1)*128 : K;
    const int nc8  = Keff / 64;    // fp8 corr chunks (64 fp8 = 64B rows)
    const int nc16 = Keff / 32;    // bf16 main chunks (32 bf16 = 64B rows)

    float acc[4][4][4];
#pragma unroll
    for (int i=0;i<4;i++)
#pragma unroll
        for (int j=0;j<4;j++)
#pragma unroll
            for (int t=0;t<4;t++) acc[i][j][t] = 0.f;

    const int arow = wm*64 + (lane & 7) + ((lane >> 3) & 1) * 8;
    const int brow = wn*32 + (lane & 7) + ((lane >> 4) & 1) * 8;

    auto load8 = [&](int c){
        const u32 base = sb + (u32)(c % 3) * STG_B;
        const int k0 = c * 64;
#pragma unroll
        for (int t = 0; t < 2; t++){
            int idx = t*256 + tid;
            int row = idx >> 2, ch = idx & 3;
            u32 d = swz(row, ch);
            size_t go = (size_t)row*K + k0 + ch*16;
            CP16(base + d,         (u64)__cvta_generic_to_global(A8_b + go));
            CP16(base + 8192 + d,  (u64)__cvta_generic_to_global(Al_b + go));
            CP16(base + 16384 + d, (u64)__cvta_generic_to_global(B8_b + go));
            CP16(base + 24576 + d, (u64)__cvta_generic_to_global(Bl_b + go));
        }
        CP_COMMIT();
    };
    auto load16 = [&](int c){
        const u32 base = sb + (u32)(c % 3) * STG_B;
        const int k0 = c * 32;
#pragma unroll
        for (int t = 0; t < 2; t++){
            int idx = t*256 + tid;
            int row = idx >> 2, ch = idx & 3;
            u32 d = swz(row, ch);
            size_t go = (size_t)row*K + k0 + ch*8;
            CP16(base + d,        (u64)__cvta_generic_to_global(Ah_b + go));
            CP16(base + 8192 + d, (u64)__cvta_generic_to_global(Bh_b + go));
        }
        CP_COMMIT();
    };

    // ---------------- phase A: fp8 corrections ----------------
    {
        int pre = nc8 < 3 ? nc8 : 3;
        for (int c = 0; c < pre; c++) load8(c);
        for (int c = 0; c < nc8; c++){
            int pend = (nc8 - c < 3 ? nc8 - c : 3) - 1;
            if (pend == 2) CP_WAIT2(); else if (pend == 1) CP_WAIT1(); else CP_WAIT0();
            __syncthreads();
            const u32 tb = sb + (u32)(c % 3) * STG_B;
#pragma unroll
            for (int s = 0; s < 2; s++){
                const int ach = 2*s + ((lane >> 4) & 1);
                const int bch = 2*s + ((lane >> 3) & 1);
                u32 af[4][4], bb[2][4];
                // A8 x Bl8
#pragma unroll
                for (int mt = 0; mt < 4; mt++) LDSM4(af[mt], tb + swz(arow + mt*16, ach));
#pragma unroll
                for (int bt = 0; bt < 2; bt++) LDSM4(bb[bt], tb + 24576 + swz(brow + bt*16, bch));
#pragma unroll
                for (int mt = 0; mt < 4; mt++)
#pragma unroll
                    for (int nt = 0; nt < 4; nt++)
                        MMA8(acc[mt][nt], af[mt], bb[nt>>1][(nt&1)*2], bb[nt>>1][(nt&1)*2+1]);
                // Al8 x B8
#pragma unroll
                for (int mt = 0; mt < 4; mt++) LDSM4(af[mt], tb + 8192 + swz(arow + mt*16, ach));
#pragma unroll
                for (int bt = 0; bt < 2; bt++) LDSM4(bb[bt], tb + 16384 + swz(brow + bt*16, bch));
#pragma unroll
                for (int mt = 0; mt < 4; mt++)
#pragma unroll
                    for (int nt = 0; nt < 4; nt++)
                        MMA8(acc[mt][nt], af[mt], bb[nt>>1][(nt&1)*2], bb[nt>>1][(nt&1)*2+1]);
            }
            __syncthreads();
            if (c + 3 < nc8) load8(c + 3);
        }
    }

    // scale corrections
#pragma unroll
    for (int i=0;i<4;i++)
#pragma unroll
        for (int j=0;j<4;j++)
#pragma unroll
            for (int t=0;t<4;t++) acc[i][j][t] *= fcorr;

    // ---------------- phase B: bf16 hi x hi ----------------
    {
        int pre = nc16 < 3 ? nc16 : 3;
        for (int c = 0; c < pre; c++) load16(c);
        for (int c = 0; c < nc16; c++){
            int pend = (nc16 - c < 3 ? nc16 - c : 3) - 1;
            if (pend == 2) CP_WAIT2(); else if (pend == 1) CP_WAIT1(); else CP_WAIT0();
            __syncthreads();
            const u32 tb = sb + (u32)(c % 3) * STG_B;
#pragma unroll
            for (int s = 0; s < 2; s++){
                const int ach = 2*s + ((lane >> 4) & 1);
                const int bch = 2*s + ((lane >> 3) & 1);
                u32 af[4][4], bb[2][4];
#pragma unroll
                for (int mt = 0; mt < 4; mt++) LDSM4(af[mt], tb + swz(arow + mt*16, ach));
#pragma unroll
                for (int bt = 0; bt < 2; bt++) LDSM4(bb[bt], tb + 8192 + swz(brow + bt*16, bch));
#pragma unroll
                for (int mt = 0; mt < 4; mt++)
#pragma unroll
                    for (int nt = 0; nt < 4; nt++)
                        MMA(acc[mt][nt], af[mt], bb[nt>>1][(nt&1)*2], bb[nt>>1][(nt&1)*2+1]);
            }
            __syncthreads();
            if (c + 3 < nc16) load16(c + 3);
        }
    }

    // ---------------- epilogue ----------------
    const int g = lane >> 2, t4 = lane & 3;
    float* Cz  = C   ? C   + (size_t)bz*sC : (float*)0;
    bf16*  Chz = Ch  ? Ch  + (size_t)bz*sC : (bf16*)0;
    u8*    C8z = C8  ? C8  + (size_t)bz*sC : (u8*)0;
    u8*    Clz = Cl8 ? Cl8 + (size_t)bz*sC : (u8*)0;
    const int row_base = bm*128 + wm*64;
    const int col_base = bn*128 + wn*32;
    const float outm256 = outm * 256.f;

#pragma unroll
    for (int mt = 0; mt < 4; mt++)
#pragma unroll
    for (int nt = 0; nt < 4; nt++){
        const int col = col_base + nt*8 + 2*t4;
        float b0 = 0.f, b1 = 0.f;
        if (bias){ b0 = bias[col]; b1 = bias[col+1]; }
#pragma unroll
        for (int h = 0; h < 2; h++){
            const int row = row_base + mt*16 + g + h*8;
            float v0 = acc[mt][nt][h*2+0] * scale + b0;
            float v1 = acc[mt][nt][h*2+1] * scale + b1;
            if (gelu){
                v0 = 0.5f*v0*(1.0f + erff(v0*0.70710678118654752f));
                v1 = 0.5f*v1*(1.0f + erff(v1*0.70710678118654752f));
            }
            const size_t off = (size_t)row*N + col;
            if (Cz) *(float2*)(Cz + off) = make_float2(v0, v1);
            if (Chz){
                bf16 h0 = __float2bfloat16_rn(v0), h1 = __float2bfloat16_rn(v1);
                *(u32*)(Chz + off) = pk(h0, h1);
                *(u16*)(C8z + off) = pk8(v0*outm, v1*outm);
                *(u16*)(Clz + off) = pk8(
                    (v0 - __bfloat162float(h0))*outm256,
                    (v1 - __bfloat162float(h1))*outm256);
            }
        }
    }
}

// ---------------- fp32 -> (hi bf16, fp8 full, fp8 lo) ----------------
__global__ __launch_bounds__(256) void convert3(
    const float* __restrict__ src, bf16* __restrict__ h,
    u8* __restrict__ f8, u8* __restrict__ l8, float m)
{
    size_t i = (size_t)blockIdx.x * 256 + threadIdx.x;   // float4 index
    float4 f = ((const float4*)src)[i];
    bf16 h0 = __float2bfloat16_rn(f.x), h1 = __float2bfloat16_rn(f.y);
    bf16 h2 = __float2bfloat16_rn(f.z), h3 = __float2bfloat16_rn(f.w);
    ((uint2*)h)[i] = make_uint2(pk(h0,h1), pk(h2,h3));
    ((u32*)f8)[i] = (u32)pk8(f.x*m, f.y*m) | ((u32)pk8(f.z*m, f.w*m) << 16);
    float m2 = m * 256.f;
    ((u32*)l8)[i] = (u32)pk8((f.x-__bfloat162float(h0))*m2, (f.y-__bfloat162float(h1))*m2)
                  | ((u32)pk8((f.z-__bfloat162float(h2))*m2, (f.w-__bfloat162float(h3))*m2) << 16);
}

// ---------------- V transpose + split ----------------
__global__ __launch_bounds__(256) void transpose3(
    const float* __restrict__ V, bf16* __restrict__ VTh,
    u8* __restrict__ VT8, u8* __restrict__ VTl, float m)
{
    __shared__ float t[32][33];
    const int b = blockIdx.z;
    const int s0 = blockIdx.x*32, d0 = blockIdx.y*32;
    const int tx = threadIdx.x, ty = threadIdx.y;
#pragma unroll
    for (int i = ty; i < 32; i += 8)
        t[i][tx] = V[(size_t)b*S_*D_ + (size_t)(s0+i)*D_ + d0 + tx];
    __syncthreads();
    const float m2 = m * 256.f;
#pragma unroll
    for (int i = ty; i < 32; i += 8){
        float v = t[tx][i];
        bf16 h = __float2bfloat16_rn(v);
        size_t off = (size_t)b*D_*S_ + (size_t)(d0+i)*S_ + s0 + tx;
        VTh[off] = h;
        VT8[off] = (u8)(pk8(v*m, 0.f) & 0xFF);
        VTl[off] = (u8)(pk8((v - __bfloat162float(h))*m2, 0.f) & 0xFF);
    }
}

// ---------------- causal softmax + split, zero tail to 128-multiple ----------------
__global__ __launch_bounds__(256) void softmax3(
    const float* __restrict__ SC, bf16* __restrict__ Ph,
    u8* __restrict__ P8, u8* __restrict__ Pl, float m)
{
    const int q = blockIdx.x, b = blockIdx.y;
    const float* row = SC + ((size_t)b*S_ + q)*S_;
    const int n = q + 1;
    const int nceil = ((q >> 7) + 1) << 7;
    const int tid = threadIdx.x;
    __shared__ float buf[S_];
    __shared__ float red[256];

    float mx = -INFINITY;
    for (int i = tid; i < n; i += 256){ float v = row[i]; buf[i] = v; mx = fmaxf(mx, v); }
    red[tid] = mx; __syncthreads();
    for (int s = 128; s > 0; s >>= 1){
        if (tid < s) red[tid] = fmaxf(red[tid], red[tid+s]);
        __syncthreads();
    }
    mx = red[0]; __syncthreads();

    float sum = 0.f;
    for (int i = tid; i < n; i += 256){ float e = __expf(buf[i] - mx); buf[i] = e; sum += e; }
    red[tid] = sum; __syncthreads();
    for (int s = 128; s > 0; s >>= 1){
        if (tid < s) red[tid] += red[tid+s];
        __syncthreads();
    }
    const float inv = 1.0f / red[0];
    const float m2 = m * 256.f;

    bf16* ph = Ph + ((size_t)b*S_ + q)*S_;
    u8* p8 = P8 + ((size_t)b*S_ + q)*S_;
    u8* pl = Pl + ((size_t)b*S_ + q)*S_;
    for (int i = tid; i < nceil; i += 256){
        if (i < n){
            float p = buf[i] * inv;
            bf16 h = __float2bfloat16_rn(p);
            ph[i] = h;
            p8[i] = (u8)(pk8(p*m, 0.f) & 0xFF);
            pl[i] = (u8)(pk8((p - __bfloat162float(h))*m2, 0.f) & 0xFF);
        } else {
            ph[i] = __float2bfloat16_rn(0.f);
            p8[i] = 0;
            pl[i] = 0;
        }
    }
}

// ---------------- launch ----------------
extern "C" void kernel_launch(void* const* d_in, const int* in_sizes, int n_in,
                              void* d_out, int out_size)
{
    const float* x  = (const float*)d_in[0];
    const float* Wq = (const float*)d_in[1];
    const float* bq = (const float*)d_in[2];
    const float* Wk = (const float*)d_in[3];
    const float* bk = (const float*)d_in[4];
    const float* Wv = (const float*)d_in[5];
    const float* bv = (const float*)d_in[6];
    const float* W1 = (const float*)d_in[7];
    const float* b1 = (const float*)d_in[8];
    const float* W2 = (const float*)d_in[9];
    const float* b2 = (const float*)d_in[10];
    float* out = (float*)d_out;

    bf16 *xh,*Wqh,*Wkh,*Wvh,*W1h,*W2h,*qh,*kh,*vth,*Ph,*aoh,*hh;
    u8 *x8,*xl,*Wq8,*Wql,*Wk8,*Wkl,*Wv8,*Wvl,*W18,*W1l,*W28,*W2l;
    u8 *q8,*ql,*k8,*kl,*vt8,*vtl,*P8,*Pl,*ao8,*aol,*h8,*hl;
    float *v,*sc;
#define GA(p, s) cudaGetSymbolAddress((void**)&p, s)
    GA(xh,g_xh); GA(x8,g_x8); GA(xl,g_xl);
    GA(Wqh,g_Wqh); GA(Wq8,g_Wq8); GA(Wql,g_Wql);
    GA(Wkh,g_Wkh); GA(Wk8,g_Wk8); GA(Wkl,g_Wkl);
    GA(Wvh,g_Wvh); GA(Wv8,g_Wv8); GA(Wvl,g_Wvl);
    GA(W1h,g_W1h); GA(W18,g_W18); GA(W1l,g_W1l);
    GA(W2h,g_W2h); GA(W28,g_W28); GA(W2l,g_W2l);
    GA(qh,g_qh); GA(q8,g_q8); GA(ql,g_ql);
    GA(kh,g_kh); GA(k8,g_k8); GA(kl,g_kl);
    GA(v,g_v);
    GA(vth,g_vth); GA(vt8,g_vt8); GA(vtl,g_vtl);
    GA(sc,g_sc);
    GA(Ph,g_Ph); GA(P8,g_P8); GA(Pl,g_Pl);
    GA(aoh,g_aoh); GA(ao8,g_ao8); GA(aol,g_aol);
    GA(hh,g_hh); GA(h8,g_h8); GA(hl,g_hl);
#undef GA

    cudaFuncSetAttribute(gemm_mma, cudaFuncAttributeMaxDynamicSharedMemorySize, SMEM_SZ);

    // scales: m_x=4, m_W=64, m_q=m_k=m_vt=m_ao=m_h=4, m_P=256
    convert3<<<(size_t)M_*D_/1024, 256>>>(x,  xh,  x8,  xl,  4.f);
    convert3<<<(size_t)D_*D_/1024, 256>>>(Wq, Wqh, Wq8, Wql, 64.f);
    convert3<<<(size_t)D_*D_/1024, 256>>>(Wk, Wkh, Wk8, Wkl, 64.f);
    convert3<<<(size_t)D_*D_/1024, 256>>>(Wv, Wvh, Wv8, Wvl, 64.f);
    convert3<<<(size_t)DFF_*D_/1024, 256>>>(W1, W1h, W18, W1l, 64.f);
    convert3<<<(size_t)D_*DFF_/1024, 256>>>(W2, W2h, W28, W2l, 64.f);

    const float f_xw = 1.f/(256.f*4.f*64.f);    // x(4) * W(64)
    const float f_qk = 1.f/(256.f*4.f*4.f);     // q(4) * k(4)
    const float f_pv = 1.f/(256.f*256.f*4.f);   // P(256) * vt(4)

    // QKV projections
    gemm_mma<<<dim3(D_/128, M_/128, 1), 256, SMEM_SZ>>>(
        xh, x8, xl, Wqh, Wq8, Wql, bq, (float*)0, qh, q8, ql,
        D_, D_, 0,0,0, 1.f, f_xw, 4.f, 0, 0);
    gemm_mma<<<dim3(D_/128, M_/128, 1), 256, SMEM_SZ>>>(
        xh, x8, xl, Wkh, Wk8, Wkl, bk, (float*)0, kh, k8, kl,
        D_, D_, 0,0,0, 1.f, f_xw, 4.f, 0, 0);
    gemm_mma<<<dim3(D_/128, M_/128, 1), 256, SMEM_SZ>>>(
        xh, x8, xl, Wvh, Wv8, Wvl, bv, v, (bf16*)0, (u8*)0, (u8*)0,
        D_, D_, 0,0,0, 1.f, f_xw, 0.f, 0, 0);

    transpose3<<<dim3(S_/32, D_/32, B_), dim3(32, 8)>>>(v, vth, vt8, vtl, 4.f);

    // scores = (1/32) q k^T, causal block skip
    gemm_mma<<<dim3(S_/128, S_/128, B_), 256, SMEM_SZ>>>(
        qh, q8, ql, kh, k8, kl, (const float*)0, sc, (bf16*)0, (u8*)0, (u8*)0,
        S_, D_, (long)S_*D_, (long)S_*D_, (long)S_*S_, 0.03125f, f_qk, 0.f, 0, 1);

    softmax3<<<dim3(S_, B_), 256>>>(sc, Ph, P8, Pl, 256.f);

    // attn = P @ vt^T, K bounded at diagonal
    gemm_mma<<<dim3(D_/128, S_/128, B_), 256, SMEM_SZ>>>(
        Ph, P8, Pl, vth, vt8, vtl, (const float*)0, (float*)0, aoh, ao8, aol,
        D_, S_, (long)S_*S_, (long)D_*S_, (long)S_*D_, 1.f, f_pv, 4.f, 0, 2);

    // MLP
    gemm_mma<<<dim3(DFF_/128, M_/128, 1), 256, SMEM_SZ>>>(
        aoh, ao8, aol, W1h, W18, W1l, b1, (float*)0, hh, h8, hl,
        DFF_, D_, 0,0,0, 1.f, f_xw, 4.f, 1, 0);
    gemm_mma<<<dim3(D_/128, M_/128, 1), 256, SMEM_SZ>>>(
        hh, h8, hl, W2h, W28, W2l, b2, out, (bf16*)0, (u8*)0, (u8*)0,
        D_, DFF_, 0,0,0, 1.f, f_xw, 0.f, 0, 0);
}

// round 7
// speedup vs baseline: 1.3906x; 1.3906x over previous
#include <cuda_runtime.h>
#include <cuda_bf16.h>
#include <math.h>

typedef unsigned int u32;
typedef unsigned long long u64;
typedef __nv_bfloat16 bf16;

#define B_   8
#define S_   2048
#define D_   1024
#define DFF_ 4096
#define M_   (B_*S_)

// ---------------- scratch (device globals) ----------------
__device__ bf16 g_xh[(size_t)M_*D_],  g_xl[(size_t)M_*D_];
__device__ bf16 g_Wqh[(size_t)D_*D_], g_Wql[(size_t)D_*D_];
__device__ bf16 g_Wkh[(size_t)D_*D_], g_Wkl[(size_t)D_*D_];
__device__ bf16 g_Wvh[(size_t)D_*D_], g_Wvl[(size_t)D_*D_];
__device__ bf16 g_W1h[(size_t)DFF_*D_], g_W1l[(size_t)DFF_*D_];
__device__ bf16 g_W2h[(size_t)D_*DFF_], g_W2l[(size_t)D_*DFF_];
__device__ bf16 g_qh[(size_t)M_*D_],  g_ql[(size_t)M_*D_];
__device__ bf16 g_kh[(size_t)M_*D_],  g_kl[(size_t)M_*D_];
__device__ float g_v[(size_t)M_*D_];
__device__ bf16 g_vth[(size_t)B_*D_*S_], g_vtl[(size_t)B_*D_*S_];
__device__ float g_sc[(size_t)B_*S_*S_];
__device__ bf16 g_Ph[(size_t)B_*S_*S_], g_Pl[(size_t)B_*S_*S_];
__device__ bf16 g_aoh[(size_t)M_*D_], g_aol[(size_t)M_*D_];
__device__ bf16 g_hh[(size_t)M_*DFF_], g_hl[(size_t)M_*DFF_];

// ---------------- helpers ----------------
__device__ __forceinline__ u32 smem_u32(const void* p){
    u32 a;
    asm("{ .reg .u64 t; cvta.to.shared.u64 t, %1; cvt.u32.u64 %0, t; }" : "=r"(a) : "l"(p));
    return a;
}
__device__ __forceinline__ u32 pk(bf16 a, bf16 b){
    unsigned short ua = *(unsigned short*)&a, ub = *(unsigned short*)&b;
    return (u32)ua | ((u32)ub << 16);
}
// 16B-chunk XOR swizzle: 64B-row tile, 4 chunks/row; conflict-free for ldmatrix
__device__ __forceinline__ u32 swz(int row, int ch){
    return (u32)((row*4 + (ch ^ ((row>>1)&3))) * 16);
}

#define CP16(dst, src) asm volatile("cp.async.cg.shared.global [%0], [%1], 16;" :: "r"(dst), "l"(src) : "memory")
#define CP_COMMIT()    asm volatile("cp.async.commit_group;" ::: "memory")
#define CP_WAIT1()     asm volatile("cp.async.wait_group 1;" ::: "memory")
#define CP_WAIT0()     asm volatile("cp.async.wait_group 0;" ::: "memory")

#define LDSM4(r, addr) asm volatile( \
    "ldmatrix.sync.aligned.m8n8.x4.shared.b16 {%0,%1,%2,%3}, [%4];" \
    : "=r"((r)[0]),"=r"((r)[1]),"=r"((r)[2]),"=r"((r)[3]) : "r"(addr))

#define MMA(c, a, b0, b1) asm volatile( \
    "mma.sync.aligned.m16n8k16.row.col.f32.bf16.bf16.f32 " \
    "{%0,%1,%2,%3},{%4,%5,%6,%7},{%8,%9},{%0,%1,%2,%3};" \
    : "+f"((c)[0]),"+f"((c)[1]),"+f"((c)[2]),"+f"((c)[3]) \
    : "r"((a)[0]),"r"((a)[1]),"r"((a)[2]),"r"((a)[3]),"r"(b0),"r"(b1))

#define TILE_B  8192       // 128 rows x 32 bf16 (64B/row)
#define STG_B   32768      // 4 tiles per stage (Ah, Al, Bh, Bl)
#define SMEM_SZ 98304      // 3 stages

// ================= bf16x3 tensor-core GEMM =================
// C = act( scale * A[M,K] @ B[N,K]^T + bias ), A/B given as hi/lo bf16 pairs.
// causal: 0 none, 1 skip bn>bm, 2 K bounded at (bm+1)*128
__global__ __launch_bounds__(256, 2) void gemm_mma(
    const bf16* __restrict__ Ah, const bf16* __restrict__ Al,
    const bf16* __restrict__ Bh, const bf16* __restrict__ Bl,
    const float* __restrict__ bias,
    float* __restrict__ C, bf16* __restrict__ Ch, bf16* __restrict__ Cl,
    int N, int K, long sA, long sB, long sC,
    float scale, int gelu, int causal)
{
    extern __shared__ char smem[];
    const int bm = blockIdx.y, bn = blockIdx.x, bz = blockIdx.z;
    if (causal == 1 && bn > bm) return;

    const int tid = threadIdx.x, lane = tid & 31, warp = tid >> 5;
    const int wm = warp >> 2, wn = warp & 3;   // 2x4 warp grid: 64m x 32n each
    const u32 sb = smem_u32(smem);

    const bf16* Ah_b = Ah + (size_t)bz*sA + (size_t)bm*128*K;
    const bf16* Al_b = Al + (size_t)bz*sA + (size_t)bm*128*K;
    const bf16* Bh_b = Bh + (size_t)bz*sB + (size_t)bn*128*K;
    const bf16* Bl_b = Bl + (size_t)bz*sB + (size_t)bn*128*K;

    const int Keff = (causal == 2) ? (bm + 1)*128 : K;
    const int nc = Keff / 32;

    float acc[4][4][4];
#pragma unroll
    for (int i=0;i<4;i++)
#pragma unroll
        for (int j=0;j<4;j++)
#pragma unroll
            for (int t=0;t<4;t++) acc[i][j][t] = 0.f;

    auto load_stage = [&](int c){
        const u32 base = sb + (u32)(c % 3) * STG_B;
        const int k0 = c * 32;
#pragma unroll
        for (int t = 0; t < 2; t++){
            int idx = t*256 + tid;
            int row = idx >> 2, ch = idx & 3;
            u32 d = swz(row, ch);
            size_t go = (size_t)row*K + k0 + ch*8;
            CP16(base + d,           (u64)__cvta_generic_to_global(Ah_b + go));
            CP16(base + TILE_B + d,  (u64)__cvta_generic_to_global(Al_b + go));
            CP16(base + 2*TILE_B + d,(u64)__cvta_generic_to_global(Bh_b + go));
            CP16(base + 3*TILE_B + d,(u64)__cvta_generic_to_global(Bl_b + go));
        }
        CP_COMMIT();
    };

    load_stage(0);
    if (nc > 1) load_stage(1);

    const int arow = wm*64 + (lane & 7) + ((lane >> 3) & 1) * 8;
    const int brow = wn*32 + (lane & 7) + ((lane >> 4) & 1) * 8;

    for (int c = 0; c < nc; c++){
        // stage c must be complete; stage c+1 (if any) may still be in flight
        if (c + 1 < nc) CP_WAIT1(); else CP_WAIT0();
        __syncthreads();   // single barrier: data visible AND all warps done reading buf (c-1)%3
        if (c + 2 < nc) load_stage(c + 2);   // overwrites buf (c-1)%3 — safe after barrier

        const u32 tAh = sb + (u32)(c % 3) * STG_B;
        const u32 tAl = tAh + TILE_B;
        const u32 tBh = tAh + 2*TILE_B;
        const u32 tBl = tAh + 3*TILE_B;

#pragma unroll
        for (int s = 0; s < 2; s++){
            const int ach = 2*s + ((lane >> 4) & 1);
            const int bch = 2*s + ((lane >> 3) & 1);

            u32 ah[4][4], bh[2][4];
#pragma unroll
            for (int mt = 0; mt < 4; mt++) LDSM4(ah[mt], tAh + swz(arow + mt*16, ach));
#pragma unroll
            for (int bt = 0; bt < 2; bt++) LDSM4(bh[bt], tBh + swz(brow + bt*16, bch));
#pragma unroll
            for (int mt = 0; mt < 4; mt++)
#pragma unroll
                for (int nt = 0; nt < 4; nt++)
                    MMA(acc[mt][nt], ah[mt], bh[nt>>1][(nt&1)*2], bh[nt>>1][(nt&1)*2+1]);

            u32 bl[2][4];
#pragma unroll
            for (int bt = 0; bt < 2; bt++) LDSM4(bl[bt], tBl + swz(brow + bt*16, bch));
#pragma unroll
            for (int mt = 0; mt < 4; mt++)
#pragma unroll
                for (int nt = 0; nt < 4; nt++)
                    MMA(acc[mt][nt], ah[mt], bl[nt>>1][(nt&1)*2], bl[nt>>1][(nt&1)*2+1]);

            u32 al[4][4];
#pragma unroll
            for (int mt = 0; mt < 4; mt++) LDSM4(al[mt], tAl + swz(arow + mt*16, ach));
#pragma unroll
            for (int mt = 0; mt < 4; mt++)
#pragma unroll
                for (int nt = 0; nt < 4; nt++)
                    MMA(acc[mt][nt], al[mt], bh[nt>>1][(nt&1)*2], bh[nt>>1][(nt&1)*2+1]);
        }
    }

    // ---------------- epilogue ----------------
    const int g = lane >> 2, t4 = lane & 3;
    float* Cz  = C  ? C  + (size_t)bz*sC : (float*)0;
    bf16*  Chz = Ch ? Ch + (size_t)bz*sC : (bf16*)0;
    bf16*  Clz = Cl ? Cl + (size_t)bz*sC : (bf16*)0;
    const int row_base = bm*128 + wm*64;
    const int col_base = bn*128 + wn*32;

#pragma unroll
    for (int mt = 0; mt < 4; mt++)
#pragma unroll
    for (int nt = 0; nt < 4; nt++){
        const int col = col_base + nt*8 + 2*t4;
        float b0 = 0.f, b1 = 0.f;
        if (bias){ b0 = bias[col]; b1 = bias[col+1]; }
#pragma unroll
        for (int h = 0; h < 2; h++){
            const int row = row_base + mt*16 + g + h*8;
            float v0 = acc[mt][nt][h*2+0] * scale + b0;
            float v1 = acc[mt][nt][h*2+1] * scale + b1;
            if (gelu){
                v0 = 0.5f*v0*(1.0f + erff(v0*0.70710678118654752f));
                v1 = 0.5f*v1*(1.0f + erff(v1*0.70710678118654752f));
            }
            const size_t off = (size_t)row*N + col;
            if (Cz) *(float2*)(Cz + off) = make_float2(v0, v1);
            if (Chz){
                bf16 h0 = __float2bfloat16_rn(v0), h1 = __float2bfloat16_rn(v1);
                *(u32*)(Chz + off) = pk(h0, h1);
                *(u32*)(Clz + off) = pk(__float2bfloat16_rn(v0 - __bfloat162float(h0)),
                                        __float2bfloat16_rn(v1 - __bfloat162float(h1)));
            }
        }
    }
}

// ---------------- elementwise fp32 -> (hi,lo) bf16 ----------------
__global__ __launch_bounds__(256) void convert_split(
    const float* __restrict__ src, bf16* __restrict__ h, bf16* __restrict__ l)
{
    size_t i = (size_t)blockIdx.x * 256 + threadIdx.x;   // float4 index
    float4 f = ((const float4*)src)[i];
    bf16 h0 = __float2bfloat16_rn(f.x), h1 = __float2bfloat16_rn(f.y);
    bf16 h2 = __float2bfloat16_rn(f.z), h3 = __float2bfloat16_rn(f.w);
    ((uint2*)h)[i] = make_uint2(pk(h0,h1), pk(h2,h3));
    ((uint2*)l)[i] = make_uint2(
        pk(__float2bfloat16_rn(f.x - __bfloat162float(h0)),
           __float2bfloat16_rn(f.y - __bfloat162float(h1))),
        pk(__float2bfloat16_rn(f.z - __bfloat162float(h2)),
           __float2bfloat16_rn(f.w - __bfloat162float(h3))));
}

// ---------------- V transpose + split: vt[b][d][s] = v[b][s][d] ----------------
__global__ __launch_bounds__(256) void transpose_split(
    const float* __restrict__ V, bf16* __restrict__ VTh, bf16* __restrict__ VTl)
{
    __shared__ float t[32][33];
    const int b = blockIdx.z;
    const int s0 = blockIdx.x*32, d0 = blockIdx.y*32;
    const int tx = threadIdx.x, ty = threadIdx.y;
#pragma unroll
    for (int i = ty; i < 32; i += 8)
        t[i][tx] = V[(size_t)b*S_*D_ + (size_t)(s0+i)*D_ + d0 + tx];
    __syncthreads();
#pragma unroll
    for (int i = ty; i < 32; i += 8){
        float v = t[tx][i];
        bf16 h = __float2bfloat16_rn(v);
        size_t off = (size_t)b*D_*S_ + (size_t)(d0+i)*S_ + s0 + tx;
        VTh[off] = h;
        VTl[off] = __float2bfloat16_rn(v - __bfloat162float(h));
    }
}

// ---------------- causal softmax + split, zero tail to 128-multiple ----------------
__global__ __launch_bounds__(256) void softmax_split(
    const float* __restrict__ SC, bf16* __restrict__ Ph, bf16* __restrict__ Pl)
{
    const int q = blockIdx.x, b = blockIdx.y;
    const float* row = SC + ((size_t)b*S_ + q)*S_;
    const int n = q + 1;
    const int nceil = ((q >> 7) + 1) << 7;
    const int tid = threadIdx.x;
    __shared__ float buf[S_];
    __shared__ float red[256];

    float m = -INFINITY;
    for (int i = tid; i < n; i += 256){ float v = row[i]; buf[i] = v; m = fmaxf(m, v); }
    red[tid] = m; __syncthreads();
    for (int s = 128; s > 0; s >>= 1){
        if (tid < s) red[tid] = fmaxf(red[tid], red[tid+s]);
        __syncthreads();
    }
    m = red[0]; __syncthreads();

    float sum = 0.f;
    for (int i = tid; i < n; i += 256){ float e = __expf(buf[i] - m); buf[i] = e; sum += e; }
    red[tid] = sum; __syncthreads();
    for (int s = 128; s > 0; s >>= 1){
        if (tid < s) red[tid] += red[tid+s];
        __syncthreads();
    }
    const float inv = 1.0f / red[0];

    bf16* ph = Ph + ((size_t)b*S_ + q)*S_;
    bf16* pl = Pl + ((size_t)b*S_ + q)*S_;
    for (int i = tid; i < nceil; i += 256){
        if (i < n){
            float p = buf[i] * inv;
            bf16 h = __float2bfloat16_rn(p);
            ph[i] = h;
            pl[i] = __float2bfloat16_rn(p - __bfloat162float(h));
        } else {
            ph[i] = __float2bfloat16_rn(0.f);
            pl[i] = __float2bfloat16_rn(0.f);
        }
    }
}

// ---------------- launch ----------------
extern "C" void kernel_launch(void* const* d_in, const int* in_sizes, int n_in,
                              void* d_out, int out_size)
{
    const float* x  = (const float*)d_in[0];
    const float* Wq = (const float*)d_in[1];
    const float* bq = (const float*)d_in[2];
    const float* Wk = (const float*)d_in[3];
    const float* bk = (const float*)d_in[4];
    const float* Wv = (const float*)d_in[5];
    const float* bv = (const float*)d_in[6];
    const float* W1 = (const float*)d_in[7];
    const float* b1 = (const float*)d_in[8];
    const float* W2 = (const float*)d_in[9];
    const float* b2 = (const float*)d_in[10];
    float* out = (float*)d_out;

    bf16 *xh,*xl,*Wqh,*Wql,*Wkh,*Wkl,*Wvh,*Wvl,*W1h,*W1l,*W2h,*W2l;
    bf16 *qh,*ql,*kh,*kl,*vth,*vtl,*Ph,*Pl,*aoh,*aol,*hh,*hl;
    float *v,*sc;
    cudaGetSymbolAddress((void**)&xh, g_xh);   cudaGetSymbolAddress((void**)&xl, g_xl);
    cudaGetSymbolAddress((void**)&Wqh,g_Wqh);  cudaGetSymbolAddress((void**)&Wql,g_Wql);
    cudaGetSymbolAddress((void**)&Wkh,g_Wkh);  cudaGetSymbolAddress((void**)&Wkl,g_Wkl);
    cudaGetSymbolAddress((void**)&Wvh,g_Wvh);  cudaGetSymbolAddress((void**)&Wvl,g_Wvl);
    cudaGetSymbolAddress((void**)&W1h,g_W1h);  cudaGetSymbolAddress((void**)&W1l,g_W1l);
    cudaGetSymbolAddress((void**)&W2h,g_W2h);  cudaGetSymbolAddress((void**)&W2l,g_W2l);
    cudaGetSymbolAddress((void**)&qh, g_qh);   cudaGetSymbolAddress((void**)&ql, g_ql);
    cudaGetSymbolAddress((void**)&kh, g_kh);   cudaGetSymbolAddress((void**)&kl, g_kl);
    cudaGetSymbolAddress((void**)&v,  g_v);
    cudaGetSymbolAddress((void**)&vth,g_vth);  cudaGetSymbolAddress((void**)&vtl,g_vtl);
    cudaGetSymbolAddress((void**)&sc, g_sc);
    cudaGetSymbolAddress((void**)&Ph, g_Ph);   cudaGetSymbolAddress((void**)&Pl, g_Pl);
    cudaGetSymbolAddress((void**)&aoh,g_aoh);  cudaGetSymbolAddress((void**)&aol,g_aol);
    cudaGetSymbolAddress((void**)&hh, g_hh);   cudaGetSymbolAddress((void**)&hl, g_hl);

    cudaFuncSetAttribute(gemm_mma, cudaFuncAttributeMaxDynamicSharedMemorySize, SMEM_SZ);

    // launches 0-4: converts (x, Wq, Wk, Wv, W1) — launch #5 is the Q GEMM (ncu -s 5 -c 1 captures it)
    convert_split<<<(size_t)M_*D_/1024, 256>>>(x,  xh,  xl);
    convert_split<<<(size_t)D_*D_/1024, 256>>>(Wq, Wqh, Wql);
    convert_split<<<(size_t)D_*D_/1024, 256>>>(Wk, Wkh, Wkl);
    convert_split<<<(size_t)D_*D_/1024, 256>>>(Wv, Wvh, Wvl);
    convert_split<<<(size_t)DFF_*D_/1024, 256>>>(W1, W1h, W1l);

    // QKV projections
    gemm_mma<<<dim3(D_/128, M_/128, 1), 256, SMEM_SZ>>>(
        xh, xl, Wqh, Wql, bq, (float*)0, qh, ql, D_, D_, 0,0,0, 1.f, 0, 0);
    gemm_mma<<<dim3(D_/128, M_/128, 1), 256, SMEM_SZ>>>(
        xh, xl, Wkh, Wkl, bk, (float*)0, kh, kl, D_, D_, 0,0,0, 1.f, 0, 0);
    gemm_mma<<<dim3(D_/128, M_/128, 1), 256, SMEM_SZ>>>(
        xh, xl, Wvh, Wvl, bv, v, (bf16*)0, (bf16*)0, D_, D_, 0,0,0, 1.f, 0, 0);

    transpose_split<<<dim3(S_/32, D_/32, B_), dim3(32, 8)>>>(v, vth, vtl);

    // scores = (1/32) q k^T, causal block skip
    gemm_mma<<<dim3(S_/128, S_/128, B_), 256, SMEM_SZ>>>(
        qh, ql, kh, kl, (const float*)0, sc, (bf16*)0, (bf16*)0,
        S_, D_, (long)S_*D_, (long)S_*D_, (long)S_*S_, 0.03125f, 0, 1);

    softmax_split<<<dim3(S_, B_), 256>>>(sc, Ph, Pl);

    // attn = P @ V^T(vt), K bounded at diagonal
    gemm_mma<<<dim3(D_/128, S_/128, B_), 256, SMEM_SZ>>>(
        Ph, Pl, vth, vtl, (const float*)0, (float*)0, aoh, aol,
        D_, S_, (long)S_*S_, (long)D_*S_, (long)S_*D_, 1.f, 0, 2);

    // MLP (convert W2 just-in-time, after the profiled window)
    gemm_mma<<<dim3(DFF_/128, M_/128, 1), 256, SMEM_SZ>>>(
        aoh, aol, W1h, W1l, b1, (float*)0, hh, hl, DFF_, D_, 0,0,0, 1.f, 1, 0);
    convert_split<<<(size_t)D_*DFF_/1024, 256>>>(W2, W2h, W2l);
    gemm_mma<<<dim3(D_/128, M_/128, 1), 256, SMEM_SZ>>>(
        hh, hl, W2h, W2l, b2, out, (bf16*)0, (bf16*)0, D_, DFF_, 0,0,0, 1.f, 0, 0);
}

// round 8
// speedup vs baseline: 2.2610x; 1.6260x over previous
#include <cuda_runtime.h>
#include <cuda_bf16.h>
#include <cuda_fp16.h>
#include <math.h>

typedef unsigned int u32;
typedef unsigned long long u64;
typedef __nv_bfloat16 bf16;

#define B_   8
#define S_   2048
#define D_   1024
#define DFF_ 4096
#define M_   (B_*S_)

// ---------------- scratch (device globals) ----------------
__device__ bf16 g_xh[(size_t)M_*D_],  g_xl[(size_t)M_*D_];
__device__ bf16 g_Wqh[(size_t)D_*D_], g_Wql[(size_t)D_*D_];
__device__ bf16 g_Wkh[(size_t)D_*D_], g_Wkl[(size_t)D_*D_];
__device__ bf16 g_Wvh[(size_t)D_*D_], g_Wvl[(size_t)D_*D_];
__device__ bf16 g_qh[(size_t)M_*D_],  g_ql[(size_t)M_*D_];
__device__ bf16 g_kh[(size_t)M_*D_],  g_kl[(size_t)M_*D_];
__device__ float g_v[(size_t)M_*D_];
__device__ float g_sc[(size_t)B_*S_*S_];
__device__ half g_W1f[(size_t)DFF_*D_];
__device__ half g_W2f[(size_t)D_*DFF_];
__device__ half g_vtf[(size_t)B_*D_*S_];
__device__ half g_Pf[(size_t)B_*S_*S_];
__device__ half g_aof[(size_t)M_*D_];
__device__ half g_hf[(size_t)M_*DFF_];

// ---------------- helpers ----------------
__device__ __forceinline__ u32 smem_u32(const void* p){
    u32 a;
    asm("{ .reg .u64 t; cvta.to.shared.u64 t, %1; cvt.u32.u64 %0, t; }" : "=r"(a) : "l"(p));
    return a;
}
__device__ __forceinline__ u32 pk(bf16 a, bf16 b){
    unsigned short ua = *(unsigned short*)&a, ub = *(unsigned short*)&b;
    return (u32)ua | ((u32)ub << 16);
}
// 16B-chunk XOR swizzle: 64B-row tile, 4 chunks/row; conflict-free for ldmatrix
__device__ __forceinline__ u32 swz(int row, int ch){
    return (u32)((row*4 + (ch ^ ((row>>1)&3))) * 16);
}

#define CP16(dst, src) asm volatile("cp.async.cg.shared.global [%0], [%1], 16;" :: "r"(dst), "l"(src) : "memory")
#define CP_COMMIT()    asm volatile("cp.async.commit_group;" ::: "memory")
#define CP_WAIT1()     asm volatile("cp.async.wait_group 1;" ::: "memory")
#define CP_WAIT0()     asm volatile("cp.async.wait_group 0;" ::: "memory")

#define LDSM4(r, addr) asm volatile( \
    "ldmatrix.sync.aligned.m8n8.x4.shared.b16 {%0,%1,%2,%3}, [%4];" \
    : "=r"((r)[0]),"=r"((r)[1]),"=r"((r)[2]),"=r"((r)[3]) : "r"(addr))

#define MMA(c, a, b0, b1) asm volatile( \
    "mma.sync.aligned.m16n8k16.row.col.f32.bf16.bf16.f32 " \
    "{%0,%1,%2,%3},{%4,%5,%6,%7},{%8,%9},{%0,%1,%2,%3};" \
    : "+f"((c)[0]),"+f"((c)[1]),"+f"((c)[2]),"+f"((c)[3]) \
    : "r"((a)[0]),"r"((a)[1]),"r"((a)[2]),"r"((a)[3]),"r"(b0),"r"(b1))

#define MMAH(c, a, b0, b1) asm volatile( \
    "mma.sync.aligned.m16n8k16.row.col.f32.f16.f16.f32 " \
    "{%0,%1,%2,%3},{%4,%5,%6,%7},{%8,%9},{%0,%1,%2,%3};" \
    : "+f"((c)[0]),"+f"((c)[1]),"+f"((c)[2]),"+f"((c)[3]) \
    : "r"((a)[0]),"r"((a)[1]),"r"((a)[2]),"r"((a)[3]),"r"(b0),"r"(b1))

#define TILE_B  8192       // 128 rows x 32 elems x 2B (64B/row)
#define STG_B   32768      // bf16x3: 4 tiles per stage
#define SMEM_SZ 98304      // 3 stages
#define STG2_B  16384      // fp16: 2 tiles per stage
#define SMEM2_SZ 49152     // 3 stages

// ================= bf16x3 tensor-core GEMM (proven R7 path) =================
// C = act( scale * A[M,K] @ B[N,K]^T + bias ), A/B hi/lo bf16 pairs.
// causal: 0 none, 1 skip bn>bm, 2 K bounded at (bm+1)*128
__global__ __launch_bounds__(256, 2) void gemm_mma(
    const bf16* __restrict__ Ah, const bf16* __restrict__ Al,
    const bf16* __restrict__ Bh, const bf16* __restrict__ Bl,
    const float* __restrict__ bias,
    float* __restrict__ C, bf16* __restrict__ Ch, bf16* __restrict__ Cl,
    int N, int K, long sA, long sB, long sC,
    float scale, int gelu, int causal)
{
    extern __shared__ char smem[];
    const int bm = blockIdx.y, bn = blockIdx.x, bz = blockIdx.z;
    if (causal == 1 && bn > bm) return;

    const int tid = threadIdx.x, lane = tid & 31, warp = tid >> 5;
    const int wm = warp >> 2, wn = warp & 3;
    const u32 sb = smem_u32(smem);

    const bf16* Ah_b = Ah + (size_t)bz*sA + (size_t)bm*128*K;
    const bf16* Al_b = Al + (size_t)bz*sA + (size_t)bm*128*K;
    const bf16* Bh_b = Bh + (size_t)bz*sB + (size_t)bn*128*K;
    const bf16* Bl_b = Bl + (size_t)bz*sB + (size_t)bn*128*K;

    const int Keff = (causal == 2) ? (bm + 1)*128 : K;
    const int nc = Keff / 32;

    float acc[4][4][4];
#pragma unroll
    for (int i=0;i<4;i++)
#pragma unroll
        for (int j=0;j<4;j++)
#pragma unroll
            for (int t=0;t<4;t++) acc[i][j][t] = 0.f;

    auto load_stage = [&](int c){
        const u32 base = sb + (u32)(c % 3) * STG_B;
        const int k0 = c * 32;
#pragma unroll
        for (int t = 0; t < 2; t++){
            int idx = t*256 + tid;
            int row = idx >> 2, ch = idx & 3;
            u32 d = swz(row, ch);
            size_t go = (size_t)row*K + k0 + ch*8;
            CP16(base + d,           (u64)__cvta_generic_to_global(Ah_b + go));
            CP16(base + TILE_B + d,  (u64)__cvta_generic_to_global(Al_b + go));
            CP16(base + 2*TILE_B + d,(u64)__cvta_generic_to_global(Bh_b + go));
            CP16(base + 3*TILE_B + d,(u64)__cvta_generic_to_global(Bl_b + go));
        }
        CP_COMMIT();
    };

    load_stage(0);
    if (nc > 1) load_stage(1);

    const int arow = wm*64 + (lane & 7) + ((lane >> 3) & 1) * 8;
    const int brow = wn*32 + (lane & 7) + ((lane >> 4) & 1) * 8;

    for (int c = 0; c < nc; c++){
        if (c + 1 < nc) CP_WAIT1(); else CP_WAIT0();
        __syncthreads();
        if (c + 2 < nc) load_stage(c + 2);

        const u32 tAh = sb + (u32)(c % 3) * STG_B;
        const u32 tAl = tAh + TILE_B;
        const u32 tBh = tAh + 2*TILE_B;
        const u32 tBl = tAh + 3*TILE_B;

#pragma unroll
        for (int s = 0; s < 2; s++){
            const int ach = 2*s + ((lane >> 4) & 1);
            const int bch = 2*s + ((lane >> 3) & 1);

            u32 ah[4][4], bh[2][4];
#pragma unroll
            for (int mt = 0; mt < 4; mt++) LDSM4(ah[mt], tAh + swz(arow + mt*16, ach));
#pragma unroll
            for (int bt = 0; bt < 2; bt++) LDSM4(bh[bt], tBh + swz(brow + bt*16, bch));
#pragma unroll
            for (int mt = 0; mt < 4; mt++)
#pragma unroll
                for (int nt = 0; nt < 4; nt++)
                    MMA(acc[mt][nt], ah[mt], bh[nt>>1][(nt&1)*2], bh[nt>>1][(nt&1)*2+1]);

            u32 bl[2][4];
#pragma unroll
            for (int bt = 0; bt < 2; bt++) LDSM4(bl[bt], tBl + swz(brow + bt*16, bch));
#pragma unroll
            for (int mt = 0; mt < 4; mt++)
#pragma unroll
                for (int nt = 0; nt < 4; nt++)
                    MMA(acc[mt][nt], ah[mt], bl[nt>>1][(nt&1)*2], bl[nt>>1][(nt&1)*2+1]);

            u32 al[4][4];
#pragma unroll
            for (int mt = 0; mt < 4; mt++) LDSM4(al[mt], tAl + swz(arow + mt*16, ach));
#pragma unroll
            for (int mt = 0; mt < 4; mt++)
#pragma unroll
                for (int nt = 0; nt < 4; nt++)
                    MMA(acc[mt][nt], al[mt], bh[nt>>1][(nt&1)*2], bh[nt>>1][(nt&1)*2+1]);
        }
    }

    // epilogue
    const int g = lane >> 2, t4 = lane & 3;
    float* Cz  = C  ? C  + (size_t)bz*sC : (float*)0;
    bf16*  Chz = Ch ? Ch + (size_t)bz*sC : (bf16*)0;
    bf16*  Clz = Cl ? Cl + (size_t)bz*sC : (bf16*)0;
    const int row_base = bm*128 + wm*64;
    const int col_base = bn*128 + wn*32;

#pragma unroll
    for (int mt = 0; mt < 4; mt++)
#pragma unroll
    for (int nt = 0; nt < 4; nt++){
        const int col = col_base + nt*8 + 2*t4;
        float b0 = 0.f, b1 = 0.f;
        if (bias){ b0 = bias[col]; b1 = bias[col+1]; }
#pragma unroll
        for (int h = 0; h < 2; h++){
            const int row = row_base + mt*16 + g + h*8;
            float v0 = acc[mt][nt][h*2+0] * scale + b0;
            float v1 = acc[mt][nt][h*2+1] * scale + b1;
            if (gelu){
                v0 = 0.5f*v0*(1.0f + erff(v0*0.70710678118654752f));
                v1 = 0.5f*v1*(1.0f + erff(v1*0.70710678118654752f));
            }
            const size_t off = (size_t)row*N + col;
            if (Cz) *(float2*)(Cz + off) = make_float2(v0, v1);
            if (Chz){
                bf16 h0 = __float2bfloat16_rn(v0), h1 = __float2bfloat16_rn(v1);
                *(u32*)(Chz + off) = pk(h0, h1);
                *(u32*)(Clz + off) = pk(__float2bfloat16_rn(v0 - __bfloat162float(h0)),
                                        __float2bfloat16_rn(v1 - __bfloat162float(h1)));
            }
        }
    }
}

// ================= fp16 single-product tensor-core GEMM =================
// C = act( scale * A[M,K] @ B[N,K]^T + bias ); fp16 inputs, fp32 accum.
__global__ __launch_bounds__(256, 2) void gemm_fp16(
    const half* __restrict__ A, const half* __restrict__ Bw,
    const float* __restrict__ bias,
    float* __restrict__ C, half* __restrict__ Ch,
    int N, int K, long sA, long sB, long sC,
    float scale, int gelu, int causal)
{
    extern __shared__ char smem[];
    const int bm = blockIdx.y, bn = blockIdx.x, bz = blockIdx.z;

    const int tid = threadIdx.x, lane = tid & 31, warp = tid >> 5;
    const int wm = warp >> 2, wn = warp & 3;
    const u32 sb = smem_u32(smem);

    const half* A_b = A  + (size_t)bz*sA + (size_t)bm*128*K;
    const half* B_b = Bw + (size_t)bz*sB + (size_t)bn*128*K;

    const int Keff = (causal == 2) ? (bm + 1)*128 : K;
    const int nc = Keff / 32;

    float acc[4][4][4];
#pragma unroll
    for (int i=0;i<4;i++)
#pragma unroll
        for (int j=0;j<4;j++)
#pragma unroll
            for (int t=0;t<4;t++) acc[i][j][t] = 0.f;

    auto load_stage = [&](int c){
        const u32 base = sb + (u32)(c % 3) * STG2_B;
        const int k0 = c * 32;
#pragma unroll
        for (int t = 0; t < 2; t++){
            int idx = t*256 + tid;
            int row = idx >> 2, ch = idx & 3;
            u32 d = swz(row, ch);
            size_t go = (size_t)row*K + k0 + ch*8;
            CP16(base + d,          (u64)__cvta_generic_to_global(A_b + go));
            CP16(base + TILE_B + d, (u64)__cvta_generic_to_global(B_b + go));
        }
        CP_COMMIT();
    };

    load_stage(0);
    if (nc > 1) load_stage(1);

    const int arow = wm*64 + (lane & 7) + ((lane >> 3) & 1) * 8;
    const int brow = wn*32 + (lane & 7) + ((lane >> 4) & 1) * 8;

    for (int c = 0; c < nc; c++){
        if (c + 1 < nc) CP_WAIT1(); else CP_WAIT0();
        __syncthreads();
        if (c + 2 < nc) load_stage(c + 2);

        const u32 tA = sb + (u32)(c % 3) * STG2_B;
        const u32 tB = tA + TILE_B;

#pragma unroll
        for (int s = 0; s < 2; s++){
            const int ach = 2*s + ((lane >> 4) & 1);
            const int bch = 2*s + ((lane >> 3) & 1);

            u32 af[4][4], bf[2][4];
#pragma unroll
            for (int mt = 0; mt < 4; mt++) LDSM4(af[mt], tA + swz(arow + mt*16, ach));
#pragma unroll
            for (int bt = 0; bt < 2; bt++) LDSM4(bf[bt], tB + swz(brow + bt*16, bch));
#pragma unroll
            for (int mt = 0; mt < 4; mt++)
#pragma unroll
                for (int nt = 0; nt < 4; nt++)
                    MMAH(acc[mt][nt], af[mt], bf[nt>>1][(nt&1)*2], bf[nt>>1][(nt&1)*2+1]);
        }
    }

    // epilogue
    const int g = lane >> 2, t4 = lane & 3;
    float* Cz = C  ? C  + (size_t)bz*sC : (float*)0;
    half* Chz = Ch ? Ch + (size_t)bz*sC : (half*)0;
    const int row_base = bm*128 + wm*64;
    const int col_base = bn*128 + wn*32;

#pragma unroll
    for (int mt = 0; mt < 4; mt++)
#pragma unroll
    for (int nt = 0; nt < 4; nt++){
        const int col = col_base + nt*8 + 2*t4;
        float b0 = 0.f, b1 = 0.f;
        if (bias){ b0 = bias[col]; b1 = bias[col+1]; }
#pragma unroll
        for (int h = 0; h < 2; h++){
            const int row = row_base + mt*16 + g + h*8;
            float v0 = acc[mt][nt][h*2+0] * scale + b0;
            float v1 = acc[mt][nt][h*2+1] * scale + b1;
            if (gelu){
                v0 = 0.5f*v0*(1.0f + erff(v0*0.70710678118654752f));
                v1 = 0.5f*v1*(1.0f + erff(v1*0.70710678118654752f));
            }
            const size_t off = (size_t)row*N + col;
            if (Cz) *(float2*)(Cz + off) = make_float2(v0, v1);
            if (Chz){
                __half2 h2 = __floats2half2_rn(v0, v1);
                *(u32*)(Chz + off) = *(u32*)&h2;
            }
        }
    }
}

// ---------------- fp32 -> (hi,lo) bf16 ----------------
__global__ __launch_bounds__(256) void convert_split(
    const float* __restrict__ src, bf16* __restrict__ h, bf16* __restrict__ l)
{
    size_t i = (size_t)blockIdx.x * 256 + threadIdx.x;
    float4 f = ((const float4*)src)[i];
    bf16 h0 = __float2bfloat16_rn(f.x), h1 = __float2bfloat16_rn(f.y);
    bf16 h2 = __float2bfloat16_rn(f.z), h3 = __float2bfloat16_rn(f.w);
    ((uint2*)h)[i] = make_uint2(pk(h0,h1), pk(h2,h3));
    ((uint2*)l)[i] = make_uint2(
        pk(__float2bfloat16_rn(f.x - __bfloat162float(h0)),
           __float2bfloat16_rn(f.y - __bfloat162float(h1))),
        pk(__float2bfloat16_rn(f.z - __bfloat162float(h2)),
           __float2bfloat16_rn(f.w - __bfloat162float(h3))));
}

// ---------------- fp32 -> fp16 ----------------
__global__ __launch_bounds__(256) void convert_half(
    const float* __restrict__ src, half* __restrict__ dst)
{
    size_t i = (size_t)blockIdx.x * 256 + threadIdx.x;
    float4 f = ((const float4*)src)[i];
    __half2 a = __floats2half2_rn(f.x, f.y);
    __half2 b = __floats2half2_rn(f.z, f.w);
    ((uint2*)dst)[i] = make_uint2(*(u32*)&a, *(u32*)&b);
}

// ---------------- V transpose -> fp16: vt[b][d][s] = v[b][s][d] ----------------
__global__ __launch_bounds__(256) void transpose_half(
    const float* __restrict__ V, half* __restrict__ VT)
{
    __shared__ float t[32][33];
    const int b = blockIdx.z;
    const int s0 = blockIdx.x*32, d0 = blockIdx.y*32;
    const int tx = threadIdx.x, ty = threadIdx.y;
#pragma unroll
    for (int i = ty; i < 32; i += 8)
        t[i][tx] = V[(size_t)b*S_*D_ + (size_t)(s0+i)*D_ + d0 + tx];
    __syncthreads();
#pragma unroll
    for (int i = ty; i < 32; i += 8)
        VT[(size_t)b*D_*S_ + (size_t)(d0+i)*S_ + s0 + tx] = __float2half_rn(t[tx][i]);
}

// ---------------- causal softmax -> fp16 P, zero tail to 128-multiple ----------------
__global__ __launch_bounds__(256) void softmax_half(
    const float* __restrict__ SC, half* __restrict__ P)
{
    const int q = blockIdx.x, b = blockIdx.y;
    const float* row = SC + ((size_t)b*S_ + q)*S_;
    const int n = q + 1;
    const int nceil = ((q >> 7) + 1) << 7;
    const int tid = threadIdx.x;
    __shared__ float buf[S_];
    __shared__ float red[256];

    float m = -INFINITY;
    for (int i = tid; i < n; i += 256){ float v = row[i]; buf[i] = v; m = fmaxf(m, v); }
    red[tid] = m; __syncthreads();
    for (int s = 128; s > 0; s >>= 1){
        if (tid < s) red[tid] = fmaxf(red[tid], red[tid+s]);
        __syncthreads();
    }
    m = red[0]; __syncthreads();

    float sum = 0.f;
    for (int i = tid; i < n; i += 256){ float e = __expf(buf[i] - m); buf[i] = e; sum += e; }
    red[tid] = sum; __syncthreads();
    for (int s = 128; s > 0; s >>= 1){
        if (tid < s) red[tid] += red[tid+s];
        __syncthreads();
    }
    const float inv = 1.0f / red[0];

    half* p = P + ((size_t)b*S_ + q)*S_;
    for (int i = tid; i < nceil; i += 256)
        p[i] = (i < n) ? __float2half_rn(buf[i] * inv) : __float2half_rn(0.f);
}

// ---------------- launch ----------------
extern "C" void kernel_launch(void* const* d_in, const int* in_sizes, int n_in,
                              void* d_out, int out_size)
{
    const float* x  = (const float*)d_in[0];
    const float* Wq = (const float*)d_in[1];
    const float* bq = (const float*)d_in[2];
    const float* Wk = (const float*)d_in[3];
    const float* bk = (const float*)d_in[4];
    const float* Wv = (const float*)d_in[5];
    const float* bv = (const float*)d_in[6];
    const float* W1 = (const float*)d_in[7];
    const float* b1 = (const float*)d_in[8];
    const float* W2 = (const float*)d_in[9];
    const float* b2 = (const float*)d_in[10];
    float* out = (float*)d_out;

    bf16 *xh,*xl,*Wqh,*Wql,*Wkh,*Wkl,*Wvh,*Wvl,*qh,*ql,*kh,*kl;
    half *W1f,*W2f,*vtf,*Pf,*aof,*hf;
    float *v,*sc;
    cudaGetSymbolAddress((void**)&xh, g_xh);   cudaGetSymbolAddress((void**)&xl, g_xl);
    cudaGetSymbolAddress((void**)&Wqh,g_Wqh);  cudaGetSymbolAddress((void**)&Wql,g_Wql);
    cudaGetSymbolAddress((void**)&Wkh,g_Wkh);  cudaGetSymbolAddress((void**)&Wkl,g_Wkl);
    cudaGetSymbolAddress((void**)&Wvh,g_Wvh);  cudaGetSymbolAddress((void**)&Wvl,g_Wvl);
    cudaGetSymbolAddress((void**)&qh, g_qh);   cudaGetSymbolAddress((void**)&ql, g_ql);
    cudaGetSymbolAddress((void**)&kh, g_kh);   cudaGetSymbolAddress((void**)&kl, g_kl);
    cudaGetSymbolAddress((void**)&v,  g_v);
    cudaGetSymbolAddress((void**)&sc, g_sc);
    cudaGetSymbolAddress((void**)&W1f,g_W1f);  cudaGetSymbolAddress((void**)&W2f,g_W2f);
    cudaGetSymbolAddress((void**)&vtf,g_vtf);
    cudaGetSymbolAddress((void**)&Pf, g_Pf);
    cudaGetSymbolAddress((void**)&aof,g_aof);
    cudaGetSymbolAddress((void**)&hf, g_hf);

    cudaFuncSetAttribute(gemm_mma,  cudaFuncAttributeMaxDynamicSharedMemorySize, SMEM_SZ);
    cudaFuncSetAttribute(gemm_fp16, cudaFuncAttributeMaxDynamicSharedMemorySize, SMEM2_SZ);

    // converts
    convert_split<<<(size_t)M_*D_/1024, 256>>>(x,  xh,  xl);
    convert_split<<<(size_t)D_*D_/1024, 256>>>(Wq, Wqh, Wql);
    convert_split<<<(size_t)D_*D_/1024, 256>>>(Wk, Wkh, Wkl);
    convert_split<<<(size_t)D_*D_/1024, 256>>>(Wv, Wvh, Wvl);
    convert_half<<<(size_t)DFF_*D_/1024, 256>>>(W1, W1f);
    convert_half<<<(size_t)D_*DFF_/1024, 256>>>(W2, W2f);

    // QKV projections (bf16x3)
    gemm_mma<<<dim3(D_/128, M_/128, 1), 256, SMEM_SZ>>>(
        xh, xl, Wqh, Wql, bq, (float*)0, qh, ql, D_, D_, 0,0,0, 1.f, 0, 0);
    gemm_mma<<<dim3(D_/128, M_/128, 1), 256, SMEM_SZ>>>(
        xh, xl, Wkh, Wkl, bk, (float*)0, kh, kl, D_, D_, 0,0,0, 1.f, 0, 0);
    gemm_mma<<<dim3(D_/128, M_/128, 1), 256, SMEM_SZ>>>(
        xh, xl, Wvh, Wvl, bv, v, (bf16*)0, (bf16*)0, D_, D_, 0,0,0, 1.f, 0, 0);

    transpose_half<<<dim3(S_/32, D_/32, B_), dim3(32, 8)>>>(v, vtf);

    // scores = (1/32) q k^T (bf16x3, causal block skip)
    gemm_mma<<<dim3(S_/128, S_/128, B_), 256, SMEM_SZ>>>(
        qh, ql, kh, kl, (const float*)0, sc, (bf16*)0, (bf16*)0,
        S_, D_, (long)S_*D_, (long)S_*D_, (long)S_*S_, 0.03125f, 0, 1);

    softmax_half<<<dim3(S_, B_), 256>>>(sc, Pf);

    // attn = P @ vt^T (fp16, K bounded at diagonal)
    gemm_fp16<<<dim3(D_/128, S_/128, B_), 256, SMEM2_SZ>>>(
        Pf, vtf, (const float*)0, (float*)0, aof,
        D_, S_, (long)S_*S_, (long)D_*S_, (long)S_*D_, 1.f, 0, 2);

    // MLP (fp16)
    gemm_fp16<<<dim3(DFF_/128, M_/128, 1), 256, SMEM2_SZ>>>(
        aof, W1f, b1, (float*)0, hf, DFF_, D_, 0,0,0, 1.f, 1, 0);
    gemm_fp16<<<dim3(D_/128, M_/128, 1), 256, SMEM2_SZ>>>(
        hf, W2f, b2, out, (half*)0, D_, DFF_, 0,0,0, 1.f, 0, 0);
}

// round 9
// speedup vs baseline: 3.2694x; 1.4460x over previous
#include <cuda_runtime.h>
#include <cuda_fp16.h>
#include <math.h>

typedef unsigned int u32;
typedef unsigned long long u64;

#define B_   8
#define S_   2048
#define D_   1024
#define DFF_ 4096
#define M_   (B_*S_)

// ---------------- scratch (device globals) ----------------
__device__ half g_xf[(size_t)M_*D_];
__device__ half g_Wqf[(size_t)D_*D_], g_Wkf[(size_t)D_*D_], g_Wvf[(size_t)D_*D_];
__device__ half g_W1f[(size_t)DFF_*D_], g_W2f[(size_t)D_*DFF_];
__device__ half g_qf[(size_t)M_*D_], g_kf[(size_t)M_*D_];
__device__ float g_v[(size_t)M_*D_];
__device__ half g_vtf[(size_t)B_*D_*S_];
__device__ float g_sc[(size_t)B_*S_*S_];
__device__ half g_Pf[(size_t)B_*S_*S_];
__device__ half g_aof[(size_t)M_*D_];
__device__ half g_hf[(size_t)M_*DFF_];

// ---------------- helpers ----------------
__device__ __forceinline__ u32 smem_u32(const void* p){
    u32 a;
    asm("{ .reg .u64 t; cvta.to.shared.u64 t, %1; cvt.u32.u64 %0, t; }" : "=r"(a) : "l"(p));
    return a;
}
// 16B-chunk XOR swizzle: 64B-row tile, 4 chunks/row; conflict-free for ldmatrix
__device__ __forceinline__ u32 swz(int row, int ch){
    return (u32)((row*4 + (ch ^ ((row>>1)&3))) * 16);
}

#define CP16(dst, src) asm volatile("cp.async.cg.shared.global [%0], [%1], 16;" :: "r"(dst), "l"(src) : "memory")
#define CP_COMMIT()    asm volatile("cp.async.commit_group;" ::: "memory")
#define CP_WAIT1()     asm volatile("cp.async.wait_group 1;" ::: "memory")
#define CP_WAIT0()     asm volatile("cp.async.wait_group 0;" ::: "memory")

#define LDSM4(r, addr) asm volatile( \
    "ldmatrix.sync.aligned.m8n8.x4.shared.b16 {%0,%1,%2,%3}, [%4];" \
    : "=r"((r)[0]),"=r"((r)[1]),"=r"((r)[2]),"=r"((r)[3]) : "r"(addr))

#define MMAH(c, a, b0, b1) asm volatile( \
    "mma.sync.aligned.m16n8k16.row.col.f32.f16.f16.f32 " \
    "{%0,%1,%2,%3},{%4,%5,%6,%7},{%8,%9},{%0,%1,%2,%3};" \
    : "+f"((c)[0]),"+f"((c)[1]),"+f"((c)[2]),"+f"((c)[3]) \
    : "r"((a)[0]),"r"((a)[1]),"r"((a)[2]),"r"((a)[3]),"r"(b0),"r"(b1))

#define TILE_B   8192      // 128 rows x 32 elems x 2B (64B/row)
#define STG2_B   16384     // 2 tiles (A, B) per stage
#define SMEM2_SZ 49152     // 3 stages

// ================= fp16 tensor-core GEMM =================
// C = act( scale * A[M,K] @ B[N,K]^T + bias ); fp16 in, fp32 accum.
// causal: 0 none, 1 skip bn>bm (scores), 2 K bounded at (bm+1)*128 (PV)
__global__ __launch_bounds__(256, 2) void gemm_fp16(
    const half* __restrict__ A, const half* __restrict__ Bw,
    const float* __restrict__ bias,
    float* __restrict__ C, half* __restrict__ Ch,
    int N, int K, long sA, long sB, long sC,
    float scale, int gelu, int causal)
{
    extern __shared__ char smem[];
    const int bm = blockIdx.y, bn = blockIdx.x, bz = blockIdx.z;
    if (causal == 1 && bn > bm) return;

    const int tid = threadIdx.x, lane = tid & 31, warp = tid >> 5;
    const int wm = warp >> 2, wn = warp & 3;   // 2x4 warps: 64m x 32n each
    const u32 sb = smem_u32(smem);

    const half* A_b = A  + (size_t)bz*sA + (size_t)bm*128*K;
    const half* B_b = Bw + (size_t)bz*sB + (size_t)bn*128*K;

    const int Keff = (causal == 2) ? (bm + 1)*128 : K;
    const int nc = Keff / 32;

    float acc[4][4][4];
#pragma unroll
    for (int i=0;i<4;i++)
#pragma unroll
        for (int j=0;j<4;j++)
#pragma unroll
            for (int t=0;t<4;t++) acc[i][j][t] = 0.f;

    auto load_stage = [&](int c){
        const u32 base = sb + (u32)(c % 3) * STG2_B;
        const int k0 = c * 32;
#pragma unroll
        for (int t = 0; t < 2; t++){
            int idx = t*256 + tid;
            int row = idx >> 2, ch = idx & 3;
            u32 d = swz(row, ch);
            size_t go = (size_t)row*K + k0 + ch*8;
            CP16(base + d,          (u64)__cvta_generic_to_global(A_b + go));
            CP16(base + TILE_B + d, (u64)__cvta_generic_to_global(B_b + go));
        }
        CP_COMMIT();
    };

    load_stage(0);
    if (nc > 1) load_stage(1);

    const int arow = wm*64 + (lane & 7) + ((lane >> 3) & 1) * 8;
    const int brow = wn*32 + (lane & 7) + ((lane >> 4) & 1) * 8;

    for (int c = 0; c < nc; c++){
        if (c + 1 < nc) CP_WAIT1(); else CP_WAIT0();
        __syncthreads();
        if (c + 2 < nc) load_stage(c + 2);

        const u32 tA = sb + (u32)(c % 3) * STG2_B;
        const u32 tB = tA + TILE_B;

#pragma unroll
        for (int s = 0; s < 2; s++){
            const int ach = 2*s + ((lane >> 4) & 1);
            const int bch = 2*s + ((lane >> 3) & 1);

            u32 af[4][4], bf[2][4];
#pragma unroll
            for (int mt = 0; mt < 4; mt++) LDSM4(af[mt], tA + swz(arow + mt*16, ach));
#pragma unroll
            for (int bt = 0; bt < 2; bt++) LDSM4(bf[bt], tB + swz(brow + bt*16, bch));
#pragma unroll
            for (int mt = 0; mt < 4; mt++)
#pragma unroll
                for (int nt = 0; nt < 4; nt++)
                    MMAH(acc[mt][nt], af[mt], bf[nt>>1][(nt&1)*2], bf[nt>>1][(nt&1)*2+1]);
        }
    }

    // epilogue
    const int g = lane >> 2, t4 = lane & 3;
    float* Cz = C  ? C  + (size_t)bz*sC : (float*)0;
    half* Chz = Ch ? Ch + (size_t)bz*sC : (half*)0;
    const int row_base = bm*128 + wm*64;
    const int col_base = bn*128 + wn*32;

#pragma unroll
    for (int mt = 0; mt < 4; mt++)
#pragma unroll
    for (int nt = 0; nt < 4; nt++){
        const int col = col_base + nt*8 + 2*t4;
        float b0 = 0.f, b1 = 0.f;
        if (bias){ b0 = bias[col]; b1 = bias[col+1]; }
#pragma unroll
        for (int h = 0; h < 2; h++){
            const int row = row_base + mt*16 + g + h*8;
            float v0 = acc[mt][nt][h*2+0] * scale + b0;
            float v1 = acc[mt][nt][h*2+1] * scale + b1;
            if (gelu){
                v0 = 0.5f*v0*(1.0f + erff(v0*0.70710678118654752f));
                v1 = 0.5f*v1*(1.0f + erff(v1*0.70710678118654752f));
            }
            const size_t off = (size_t)row*N + col;
            if (Cz) *(float2*)(Cz + off) = make_float2(v0, v1);
            if (Chz){
                __half2 h2 = __floats2half2_rn(v0, v1);
                *(u32*)(Chz + off) = *(u32*)&h2;
            }
        }
    }
}

// ---------------- fp32 -> fp16 ----------------
__global__ __launch_bounds__(256) void convert_half(
    const float* __restrict__ src, half* __restrict__ dst)
{
    size_t i = (size_t)blockIdx.x * 256 + threadIdx.x;
    float4 f = ((const float4*)src)[i];
    __half2 a = __floats2half2_rn(f.x, f.y);
    __half2 b = __floats2half2_rn(f.z, f.w);
    ((uint2*)dst)[i] = make_uint2(*(u32*)&a, *(u32*)&b);
}

// ---------------- V transpose -> fp16: vt[b][d][s] = v[b][s][d] ----------------
__global__ __launch_bounds__(256) void transpose_half(
    const float* __restrict__ V, half* __restrict__ VT)
{
    __shared__ float t[32][33];
    const int b = blockIdx.z;
    const int s0 = blockIdx.x*32, d0 = blockIdx.y*32;
    const int tx = threadIdx.x, ty = threadIdx.y;
#pragma unroll
    for (int i = ty; i < 32; i += 8)
        t[i][tx] = V[(size_t)b*S_*D_ + (size_t)(s0+i)*D_ + d0 + tx];
    __syncthreads();
#pragma unroll
    for (int i = ty; i < 32; i += 8)
        VT[(size_t)b*D_*S_ + (size_t)(d0+i)*S_ + s0 + tx] = __float2half_rn(t[tx][i]);
}

// ---------------- causal softmax -> fp16 P, zero tail to 128-multiple ----------------
__global__ __launch_bounds__(256) void softmax_half(
    const float* __restrict__ SC, half* __restrict__ P)
{
    const int q = blockIdx.x, b = blockIdx.y;
    const float* row = SC + ((size_t)b*S_ + q)*S_;
    const int n = q + 1;
    const int nceil = ((q >> 7) + 1) << 7;
    const int tid = threadIdx.x;
    __shared__ float buf[S_];
    __shared__ float red[256];

    float m = -INFINITY;
    for (int i = tid; i < n; i += 256){ float v = row[i]; buf[i] = v; m = fmaxf(m, v); }
    red[tid] = m; __syncthreads();
    for (int s = 128; s > 0; s >>= 1){
        if (tid < s) red[tid] = fmaxf(red[tid], red[tid+s]);
        __syncthreads();
    }
    m = red[0]; __syncthreads();

    float sum = 0.f;
    for (int i = tid; i < n; i += 256){ float e = __expf(buf[i] - m); buf[i] = e; sum += e; }
    red[tid] = sum; __syncthreads();
    for (int s = 128; s > 0; s >>= 1){
        if (tid < s) red[tid] += red[tid+s];
        __syncthreads();
    }
    const float inv = 1.0f / red[0];

    half* p = P + ((size_t)b*S_ + q)*S_;
    for (int i = tid; i < nceil; i += 256)
        p[i] = (i < n) ? __float2half_rn(buf[i] * inv) : __float2half_rn(0.f);
}

// ---------------- launch ----------------
extern "C" void kernel_launch(void* const* d_in, const int* in_sizes, int n_in,
                              void* d_out, int out_size)
{
    const float* x  = (const float*)d_in[0];
    const float* Wq = (const float*)d_in[1];
    const float* bq = (const float*)d_in[2];
    const float* Wk = (const float*)d_in[3];
    const float* bk = (const float*)d_in[4];
    const float* Wv = (const float*)d_in[5];
    const float* bv = (const float*)d_in[6];
    const float* W1 = (const float*)d_in[7];
    const float* b1 = (const float*)d_in[8];
    const float* W2 = (const float*)d_in[9];
    const float* b2 = (const float*)d_in[10];
    float* out = (float*)d_out;

    half *xf,*Wqf,*Wkf,*Wvf,*W1f,*W2f,*qf,*kf,*vtf,*Pf,*aof,*hf;
    float *v,*sc;
    cudaGetSymbolAddress((void**)&xf, g_xf);
    cudaGetSymbolAddress((void**)&Wqf,g_Wqf);
    cudaGetSymbolAddress((void**)&Wkf,g_Wkf);
    cudaGetSymbolAddress((void**)&Wvf,g_Wvf);
    cudaGetSymbolAddress((void**)&W1f,g_W1f);
    cudaGetSymbolAddress((void**)&W2f,g_W2f);
    cudaGetSymbolAddress((void**)&qf, g_qf);
    cudaGetSymbolAddress((void**)&kf, g_kf);
    cudaGetSymbolAddress((void**)&v,  g_v);
    cudaGetSymbolAddress((void**)&vtf,g_vtf);
    cudaGetSymbolAddress((void**)&sc, g_sc);
    cudaGetSymbolAddress((void**)&Pf, g_Pf);
    cudaGetSymbolAddress((void**)&aof,g_aof);
    cudaGetSymbolAddress((void**)&hf, g_hf);

    cudaFuncSetAttribute(gemm_fp16, cudaFuncAttributeMaxDynamicSharedMemorySize, SMEM2_SZ);

    // launches 0-4: converts — launch #5 is the Q GEMM (ncu -s 5 -c 1 lands there)
    convert_half<<<(size_t)M_*D_/1024, 256>>>(x,  xf);
    convert_half<<<(size_t)D_*D_/1024, 256>>>(Wq, Wqf);
    convert_half<<<(size_t)D_*D_/1024, 256>>>(Wk, Wkf);
    convert_half<<<(size_t)D_*D_/1024, 256>>>(Wv, Wvf);
    convert_half<<<(size_t)DFF_*D_/1024, 256>>>(W1, W1f);

    // QKV projections (fp16)
    gemm_fp16<<<dim3(D_/128, M_/128, 1), 256, SMEM2_SZ>>>(
        xf, Wqf, bq, (float*)0, qf, D_, D_, 0,0,0, 1.f, 0, 0);
    gemm_fp16<<<dim3(D_/128, M_/128, 1), 256, SMEM2_SZ>>>(
        xf, Wkf, bk, (float*)0, kf, D_, D_, 0,0,0, 1.f, 0, 0);
    gemm_fp16<<<dim3(D_/128, M_/128, 1), 256, SMEM2_SZ>>>(
        xf, Wvf, bv, v, (half*)0, D_, D_, 0,0,0, 1.f, 0, 0);

    transpose_half<<<dim3(S_/32, D_/32, B_), dim3(32, 8)>>>(v, vtf);

    // scores = (1/32) q k^T (fp16, causal block skip)
    gemm_fp16<<<dim3(S_/128, S_/128, B_), 256, SMEM2_SZ>>>(
        qf, kf, (const float*)0, sc, (half*)0,
        S_, D_, (long)S_*D_, (long)S_*D_, (long)S_*S_, 0.03125f, 0, 1);

    softmax_half<<<dim3(S_, B_), 256>>>(sc, Pf);

    // attn = P @ vt^T (fp16, K bounded at diagonal)
    gemm_fp16<<<dim3(D_/128, S_/128, B_), 256, SMEM2_SZ>>>(
        Pf, vtf, (const float*)0, (float*)0, aof,
        D_, S_, (long)S_*S_, (long)D_*S_, (long)S_*D_, 1.f, 0, 2);

    // MLP (fp16); W2 converted after the profiled window
    gemm_fp16<<<dim3(DFF_/128, M_/128, 1), 256, SMEM2_SZ>>>(
        aof, W1f, b1, (float*)0, hf, DFF_, D_, 0,0,0, 1.f, 1, 0);
    convert_half<<<(size_t)D_*DFF_/1024, 256>>>(W2, W2f);
    gemm_fp16<<<dim3(D_/128, M_/128, 1), 256, SMEM2_SZ>>>(
        hf, W2f, b2, out, (half*)0, D_, DFF_, 0,0,0, 1.f, 0, 0);
}

// round 10
// speedup vs baseline: 3.4411x; 1.0525x over previous
#include <cuda_runtime.h>
#include <cuda_fp16.h>
#include <math.h>

typedef unsigned int u32;
typedef unsigned long long u64;

#define B_   8
#define S_   2048
#define D_   1024
#define DFF_ 4096
#define M_   (B_*S_)

// ---------------- scratch (device globals) ----------------
__device__ half g_xf[(size_t)M_*D_];
__device__ half g_Wqkv[(size_t)3*D_*D_];       // [3072][1024] concat
__device__ half g_W1f[(size_t)DFF_*D_], g_W2f[(size_t)D_*DFF_];
__device__ half g_qf[(size_t)M_*D_], g_kf[(size_t)M_*D_], g_vf[(size_t)M_*D_];
__device__ half g_vtf[(size_t)B_*D_*S_];
__device__ half g_scf[(size_t)B_*S_*S_];        // scores, softmaxed in place
__device__ half g_aof[(size_t)M_*D_];
__device__ half g_hf[(size_t)M_*DFF_];

// ---------------- helpers ----------------
__device__ __forceinline__ u32 smem_u32(const void* p){
    u32 a;
    asm("{ .reg .u64 t; cvta.to.shared.u64 t, %1; cvt.u32.u64 %0, t; }" : "=r"(a) : "l"(p));
    return a;
}
// 16B-chunk XOR swizzle on 64B-row tiles (4 chunks/row); conflict-free for ldmatrix
__device__ __forceinline__ u32 swz(int row, int ch){
    return (u32)((row*4 + (ch ^ ((row>>1)&3))) * 16);
}

#define CP16(dst, src) asm volatile("cp.async.cg.shared.global [%0], [%1], 16;" :: "r"(dst), "l"(src) : "memory")
#define CP_COMMIT()    asm volatile("cp.async.commit_group;" ::: "memory")
#define CP_WAIT1()     asm volatile("cp.async.wait_group 1;" ::: "memory")
#define CP_WAIT0()     asm volatile("cp.async.wait_group 0;" ::: "memory")

#define LDSM4(r, addr) asm volatile( \
    "ldmatrix.sync.aligned.m8n8.x4.shared.b16 {%0,%1,%2,%3}, [%4];" \
    : "=r"((r)[0]),"=r"((r)[1]),"=r"((r)[2]),"=r"((r)[3]) : "r"(addr))

#define MMAH(c, a, b0, b1) asm volatile( \
    "mma.sync.aligned.m16n8k16.row.col.f32.f16.f16.f32 " \
    "{%0,%1,%2,%3},{%4,%5,%6,%7},{%8,%9},{%0,%1,%2,%3};" \
    : "+f"((c)[0]),"+f"((c)[1]),"+f"((c)[2]),"+f"((c)[3]) \
    : "r"((a)[0]),"r"((a)[1]),"r"((a)[2]),"r"((a)[3]),"r"(b0),"r"(b1))

#define HTILE_B  8192      // 128 rows x 32 halves (64B/row)
#define STG_B    32768     // K=64 stage: A(lo,hi) + B(lo,hi) = 4 tiles
#define SMEM_SZ  98304     // 3 stages

// ================= fp16 tensor-core GEMM, K-chunk 64 =================
// C = act( scale * A[M,K] @ B[N,K]^T + bias ); fp16 in, fp32 accum.
// causal: 0 none, 1 skip bn>bm (scores), 2 K bounded at (bm+1)*128 (PV, longest-first)
// qkv: epilogue routes bn/8 -> (o_q,o_k,o_v) with biases (b_q,b_k,b_v), stride D_
__global__ __launch_bounds__(256, 2) void gemm_fp16(
    const half* __restrict__ A, const half* __restrict__ Bw,
    const float* __restrict__ b_q, const float* __restrict__ b_k, const float* __restrict__ b_v,
    float* __restrict__ C, half* __restrict__ o_q, half* __restrict__ o_k, half* __restrict__ o_v,
    int N, int K, long sA, long sB, long sC,
    float scale, int gelu, int causal, int qkv)
{
    extern __shared__ char smem[];
    const int bn = blockIdx.x, bz = blockIdx.z;
    const int bm = (causal == 2) ? (gridDim.y - 1 - blockIdx.y) : blockIdx.y;
    if (causal == 1 && bn > bm) return;

    const int tid = threadIdx.x, lane = tid & 31, warp = tid >> 5;
    const int wm = warp >> 2, wn = warp & 3;   // 2x4 warps: 64m x 32n each
    const u32 sb = smem_u32(smem);

    const half* A_b = A  + (size_t)bz*sA + (size_t)bm*128*K;
    const half* B_b = Bw + (size_t)bz*sB + (size_t)bn*128*K;

    const int Keff = (causal == 2) ? (bm + 1)*128 : K;
    const int nc = Keff / 64;

    float acc[4][4][4];
#pragma unroll
    for (int i=0;i<4;i++)
#pragma unroll
        for (int j=0;j<4;j++)
#pragma unroll
            for (int t=0;t<4;t++) acc[i][j][t] = 0.f;

    auto load_stage = [&](int c){
        const u32 base = sb + (u32)(c % 3) * STG_B;
        const int k0 = c * 64;
#pragma unroll
        for (int t = 0; t < 4; t++){
            int idx = t*256 + tid;          // 0..1023
            int row = idx >> 3, ch = idx & 7;
            u32 d = (u32)((ch >> 2) * HTILE_B) + swz(row, ch & 3);
            size_t go = (size_t)row*K + k0 + ch*8;
            CP16(base + d,              (u64)__cvta_generic_to_global(A_b + go));
            CP16(base + 2*HTILE_B + d,  (u64)__cvta_generic_to_global(B_b + go));
        }
        CP_COMMIT();
    };

    load_stage(0);
    if (nc > 1) load_stage(1);

    const int arow = wm*64 + (lane & 7) + ((lane >> 3) & 1) * 8;
    const int brow = wn*32 + (lane & 7) + ((lane >> 4) & 1) * 8;

    for (int c = 0; c < nc; c++){
        if (c + 1 < nc) CP_WAIT1(); else CP_WAIT0();
        __syncthreads();
        if (c + 2 < nc) load_stage(c + 2);

        const u32 stg = sb + (u32)(c % 3) * STG_B;

#pragma unroll
        for (int s = 0; s < 4; s++){
            const u32 tA = stg + (u32)((s >> 1) * HTILE_B);
            const u32 tB = tA + 2*HTILE_B;
            const int sl = s & 1;
            const int ach = 2*sl + ((lane >> 4) & 1);
            const int bch = 2*sl + ((lane >> 3) & 1);

            u32 af[4][4], bf[2][4];
#pragma unroll
            for (int mt = 0; mt < 4; mt++) LDSM4(af[mt], tA + swz(arow + mt*16, ach));
#pragma unroll
            for (int bt = 0; bt < 2; bt++) LDSM4(bf[bt], tB + swz(brow + bt*16, bch));
#pragma unroll
            for (int mt = 0; mt < 4; mt++)
#pragma unroll
                for (int nt = 0; nt < 4; nt++)
                    MMAH(acc[mt][nt], af[mt], bf[nt>>1][(nt&1)*2], bf[nt>>1][(nt&1)*2+1]);
        }
    }

    // ---------------- epilogue ----------------
    const int g = lane >> 2, t4 = lane & 3;
    const int row_base = bm*128 + wm*64;

    if (qkv){
        const int which = bn >> 3;
        half* dst = (which == 0) ? o_q : (which == 1) ? o_k : o_v;
        const float* bb = (which == 0) ? b_q : (which == 1) ? b_k : b_v;
        const int col_base = (bn & 7)*128 + wn*32;
#pragma unroll
        for (int mt = 0; mt < 4; mt++)
#pragma unroll
        for (int nt = 0; nt < 4; nt++){
            const int col = col_base + nt*8 + 2*t4;
            const float b0 = bb[col], b1 = bb[col+1];
#pragma unroll
            for (int h = 0; h < 2; h++){
                const int row = row_base + mt*16 + g + h*8;
                __half2 h2 = __floats2half2_rn(acc[mt][nt][h*2+0] + b0,
                                               acc[mt][nt][h*2+1] + b1);
                *(u32*)(dst + (size_t)row*D_ + col) = *(u32*)&h2;
            }
        }
        return;
    }

    float* Cz = C   ? C   + (size_t)bz*sC : (float*)0;
    half* Chz = o_q ? o_q + (size_t)bz*sC : (half*)0;
    const int col_base = bn*128 + wn*32;

#pragma unroll
    for (int mt = 0; mt < 4; mt++)
#pragma unroll
    for (int nt = 0; nt < 4; nt++){
        const int col = col_base + nt*8 + 2*t4;
        float b0 = 0.f, b1 = 0.f;
        if (b_q){ b0 = b_q[col]; b1 = b_q[col+1]; }
#pragma unroll
        for (int h = 0; h < 2; h++){
            const int row = row_base + mt*16 + g + h*8;
            float v0 = acc[mt][nt][h*2+0] * scale + b0;
            float v1 = acc[mt][nt][h*2+1] * scale + b1;
            if (gelu){
                v0 = 0.5f*v0*(1.0f + erff(v0*0.70710678118654752f));
                v1 = 0.5f*v1*(1.0f + erff(v1*0.70710678118654752f));
            }
            const size_t off = (size_t)row*N + col;
            if (Cz) *(float2*)(Cz + off) = make_float2(v0, v1);
            if (Chz){
                __half2 h2 = __floats2half2_rn(v0, v1);
                *(u32*)(Chz + off) = *(u32*)&h2;
            }
        }
    }
}

// ---------------- fp32 -> fp16 ----------------
__global__ __launch_bounds__(256) void convert_half(
    const float* __restrict__ src, half* __restrict__ dst)
{
    size_t i = (size_t)blockIdx.x * 256 + threadIdx.x;
    float4 f = ((const float4*)src)[i];
    __half2 a = __floats2half2_rn(f.x, f.y);
    __half2 b = __floats2half2_rn(f.z, f.w);
    ((uint2*)dst)[i] = make_uint2(*(u32*)&a, *(u32*)&b);
}

// ---------------- V transpose fp16: vt[b][d][s] = v[b][s][d] ----------------
__global__ __launch_bounds__(256) void transpose_half(
    const half* __restrict__ V, half* __restrict__ VT)
{
    __shared__ half t[32][33];
    const int b = blockIdx.z;
    const int s0 = blockIdx.x*32, d0 = blockIdx.y*32;
    const int tx = threadIdx.x, ty = threadIdx.y;
#pragma unroll
    for (int i = ty; i < 32; i += 8)
        t[i][tx] = V[(size_t)b*S_*D_ + (size_t)(s0+i)*D_ + d0 + tx];
    __syncthreads();
#pragma unroll
    for (int i = ty; i < 32; i += 8)
        VT[(size_t)b*D_*S_ + (size_t)(d0+i)*S_ + s0 + tx] = t[tx][i];
}

// ---------------- causal softmax, fp16 in-place; zero tail to 128-multiple ----------------
__global__ __launch_bounds__(256) void softmax_half(half* __restrict__ SC)
{
    const int q = blockIdx.x, b = blockIdx.y;
    half* row = SC + ((size_t)b*S_ + q)*S_;
    const int n = q + 1;
    const int nceil = ((q >> 7) + 1) << 7;
    const int tid = threadIdx.x;
    __shared__ float buf[S_];
    __shared__ float red[256];

    float m = -INFINITY;
    for (int i = tid; i < n; i += 256){ float v = __half2float(row[i]); buf[i] = v; m = fmaxf(m, v); }
    red[tid] = m; __syncthreads();
    for (int s = 128; s > 0; s >>= 1){
        if (tid < s) red[tid] = fmaxf(red[tid], red[tid+s]);
        __syncthreads();
    }
    m = red[0]; __syncthreads();

    float sum = 0.f;
    for (int i = tid; i < n; i += 256){ float e = __expf(buf[i] - m); buf[i] = e; sum += e; }
    red[tid] = sum; __syncthreads();
    for (int s = 128; s > 0; s >>= 1){
        if (tid < s) red[tid] += red[tid+s];
        __syncthreads();
    }
    const float inv = 1.0f / red[0];

    for (int i = tid; i < nceil; i += 256)
        row[i] = (i < n) ? __float2half_rn(buf[i] * inv) : __float2half_rn(0.f);
}

// ---------------- launch ----------------
extern "C" void kernel_launch(void* const* d_in, const int* in_sizes, int n_in,
                              void* d_out, int out_size)
{
    const float* x  = (const float*)d_in[0];
    const float* Wq = (const float*)d_in[1];
    const float* bq = (const float*)d_in[2];
    const float* Wk = (const float*)d_in[3];
    const float* bk = (const float*)d_in[4];
    const float* Wv = (const float*)d_in[5];
    const float* bv = (const float*)d_in[6];
    const float* W1 = (const float*)d_in[7];
    const float* b1 = (const float*)d_in[8];
    const float* W2 = (const float*)d_in[9];
    const float* b2 = (const float*)d_in[10];
    float* out = (float*)d_out;

    half *xf,*Wqkv,*W1f,*W2f,*qf,*kf,*vf,*vtf,*scf,*aof,*hf;
    cudaGetSymbolAddress((void**)&xf,  g_xf);
    cudaGetSymbolAddress((void**)&Wqkv,g_Wqkv);
    cudaGetSymbolAddress((void**)&W1f, g_W1f);
    cudaGetSymbolAddress((void**)&W2f, g_W2f);
    cudaGetSymbolAddress((void**)&qf,  g_qf);
    cudaGetSymbolAddress((void**)&kf,  g_kf);
    cudaGetSymbolAddress((void**)&vf,  g_vf);
    cudaGetSymbolAddress((void**)&vtf, g_vtf);
    cudaGetSymbolAddress((void**)&scf, g_scf);
    cudaGetSymbolAddress((void**)&aof, g_aof);
    cudaGetSymbolAddress((void**)&hf,  g_hf);

    cudaFuncSetAttribute(gemm_fp16, cudaFuncAttributeMaxDynamicSharedMemorySize, SMEM_SZ);

    // launches 0-4: converts — launch #5 = fused QKV GEMM (ncu -s 5 -c 1 lands there)
    convert_half<<<(size_t)M_*D_/1024, 256>>>(x,  xf);
    convert_half<<<(size_t)D_*D_/1024, 256>>>(Wq, Wqkv);
    convert_half<<<(size_t)D_*D_/1024, 256>>>(Wk, Wqkv + (size_t)D_*D_);
    convert_half<<<(size_t)D_*D_/1024, 256>>>(Wv, Wqkv + (size_t)2*D_*D_);
    convert_half<<<(size_t)DFF_*D_/1024, 256>>>(W1, W1f);

    // fused QKV projection: [16384 x 1024] @ [3072 x 1024]^T, epilogue routes q/k/v
    gemm_fp16<<<dim3(3*D_/128, M_/128, 1), 256, SMEM_SZ>>>(
        xf, Wqkv, bq, bk, bv, (float*)0, qf, kf, vf,
        3*D_, D_, 0,0,0, 1.f, 0, 0, 1);

    transpose_half<<<dim3(S_/32, D_/32, B_), dim3(32, 8)>>>(vf, vtf);

    // scores = (1/32) q k^T -> fp16 scf (causal block skip)
    gemm_fp16<<<dim3(S_/128, S_/128, B_), 256, SMEM_SZ>>>(
        qf, kf, (float*)0, (float*)0, (float*)0, (float*)0, scf, (half*)0, (half*)0,
        S_, D_, (long)S_*D_, (long)S_*D_, (long)S_*S_, 0.03125f, 0, 1, 0);

    softmax_half<<<dim3(S_, B_), 256>>>(scf);

    // attn = P @ vt^T (K bounded at diagonal, longest blocks first)
    gemm_fp16<<<dim3(D_/128, S_/128, B_), 256, SMEM_SZ>>>(
        scf, vtf, (float*)0, (float*)0, (float*)0, (float*)0, aof, (half*)0, (half*)0,
        D_, S_, (long)S_*S_, (long)D_*S_, (long)S_*D_, 1.f, 0, 2, 0);

    // MLP
    gemm_fp16<<<dim3(DFF_/128, M_/128, 1), 256, SMEM_SZ>>>(
        aof, W1f, b1, (float*)0, (float*)0, (float*)0, hf, (half*)0, (half*)0,
        DFF_, D_, 0,0,0, 1.f, 1, 0, 0);
    convert_half<<<(size_t)D_*DFF_/1024, 256>>>(W2, W2f);
    gemm_fp16<<<dim3(D_/128, M_/128, 1), 256, SMEM_SZ>>>(
        hf, W2f, b2, (float*)0, (float*)0, out, (half*)0, (half*)0, (half*)0,
        D_, DFF_, 0,0,0, 1.f, 0, 0, 0);
}

// round 11
// speedup vs baseline: 3.5091x; 1.0198x over previous
#include <cuda_runtime.h>
#include <cuda_fp16.h>
#include <math.h>

typedef unsigned int u32;
typedef unsigned long long u64;

#define B_   8
#define S_   2048
#define D_   1024
#define DFF_ 4096
#define M_   (B_*S_)

// ---------------- scratch (device globals) ----------------
__device__ half g_xf[(size_t)M_*D_];
__device__ half g_Wqkv[(size_t)3*D_*D_];       // [3072][1024] concat
__device__ half g_W1f[(size_t)DFF_*D_], g_W2f[(size_t)D_*DFF_];
__device__ half g_qf[(size_t)M_*D_], g_kf[(size_t)M_*D_], g_vf[(size_t)M_*D_];
__device__ half g_vtf[(size_t)B_*D_*S_];
__device__ half g_scf[(size_t)B_*S_*S_];        // scores, softmaxed in place
__device__ half g_aof[(size_t)M_*D_];
__device__ half g_hf[(size_t)M_*DFF_];

// ---------------- helpers ----------------
__device__ __forceinline__ u32 smem_u32(const void* p){
    u32 a;
    asm("{ .reg .u64 t; cvta.to.shared.u64 t, %1; cvt.u32.u64 %0, t; }" : "=r"(a) : "l"(p));
    return a;
}
// 16B-chunk XOR swizzle on 64B-row tiles (4 chunks/row); conflict-free for ldmatrix
__device__ __forceinline__ u32 swz(int row, int ch){
    return (u32)((row*4 + (ch ^ ((row>>1)&3))) * 16);
}

#define CP16(dst, src) asm volatile("cp.async.cg.shared.global [%0], [%1], 16;" :: "r"(dst), "l"(src) : "memory")
#define CP_COMMIT()    asm volatile("cp.async.commit_group;" ::: "memory")
#define CP_WAIT1()     asm volatile("cp.async.wait_group 1;" ::: "memory")
#define CP_WAIT0()     asm volatile("cp.async.wait_group 0;" ::: "memory")

#define LDSM4(r, addr) asm volatile( \
    "ldmatrix.sync.aligned.m8n8.x4.shared.b16 {%0,%1,%2,%3}, [%4];" \
    : "=r"((r)[0]),"=r"((r)[1]),"=r"((r)[2]),"=r"((r)[3]) : "r"(addr))

#define MMAH(c, a, b0, b1) asm volatile( \
    "mma.sync.aligned.m16n8k16.row.col.f32.f16.f16.f32 " \
    "{%0,%1,%2,%3},{%4,%5,%6,%7},{%8,%9},{%0,%1,%2,%3};" \
    : "+f"((c)[0]),"+f"((c)[1]),"+f"((c)[2]),"+f"((c)[3]) \
    : "r"((a)[0]),"r"((a)[1]),"r"((a)[2]),"r"((a)[3]),"r"(b0),"r"(b1))

#define HTILE_B  8192      // 128 rows x 32 halves (64B/row)
#define STG_B    32768     // K=64 stage: A(lo,hi) + B(lo,hi) = 4 tiles
#define SMEM_SZ  98304     // 3 stages

// ================= fp16 tensor-core GEMM, K-chunk 64 =================
// C = act( scale * A[M,K] @ B[N,K]^T + bias ); fp16 in, fp32 accum.
// causal: 0 none, 1 skip bn>bm (scores), 2 K bounded at (bm+1)*128 (PV, longest-first)
// qkv: epilogue routes bn/8 -> (o_q,o_k,o_v) with biases (b_q,b_k,b_v), stride D_
__global__ __launch_bounds__(256, 2) void gemm_fp16(
    const half* __restrict__ A, const half* __restrict__ Bw,
    const float* __restrict__ b_q, const float* __restrict__ b_k, const float* __restrict__ b_v,
    float* __restrict__ C, half* __restrict__ o_q, half* __restrict__ o_k, half* __restrict__ o_v,
    int N, int K, long sA, long sB, long sC,
    float scale, int gelu, int causal, int qkv)
{
    extern __shared__ char smem[];
    const int bn = blockIdx.x, bz = blockIdx.z;
    const int bm = (causal == 2) ? (gridDim.y - 1 - blockIdx.y) : blockIdx.y;
    if (causal == 1 && bn > bm) return;

    const int tid = threadIdx.x, lane = tid & 31, warp = tid >> 5;
    const int wm = warp >> 2, wn = warp & 3;   // 2x4 warps: 64m x 32n each
    const u32 sb = smem_u32(smem);

    const half* A_b = A  + (size_t)bz*sA + (size_t)bm*128*K;
    const half* B_b = Bw + (size_t)bz*sB + (size_t)bn*128*K;

    const int Keff = (causal == 2) ? (bm + 1)*128 : K;
    const int nc = Keff / 64;

    float acc[4][4][4];
#pragma unroll
    for (int i=0;i<4;i++)
#pragma unroll
        for (int j=0;j<4;j++)
#pragma unroll
            for (int t=0;t<4;t++) acc[i][j][t] = 0.f;

    auto load_stage = [&](int c){
        const u32 base = sb + (u32)(c % 3) * STG_B;
        const int k0 = c * 64;
#pragma unroll
        for (int t = 0; t < 4; t++){
            int idx = t*256 + tid;          // 0..1023
            int row = idx >> 3, ch = idx & 7;
            u32 d = (u32)((ch >> 2) * HTILE_B) + swz(row, ch & 3);
            size_t go = (size_t)row*K + k0 + ch*8;
            CP16(base + d,              (u64)__cvta_generic_to_global(A_b + go));
            CP16(base + 2*HTILE_B + d,  (u64)__cvta_generic_to_global(B_b + go));
        }
        CP_COMMIT();
    };

    load_stage(0);
    if (nc > 1) load_stage(1);

    const int arow = wm*64 + (lane & 7) + ((lane >> 3) & 1) * 8;
    const int brow = wn*32 + (lane & 7) + ((lane >> 4) & 1) * 8;

    for (int c = 0; c < nc; c++){
        if (c + 1 < nc) CP_WAIT1(); else CP_WAIT0();
        __syncthreads();
        if (c + 2 < nc) load_stage(c + 2);

        const u32 stg = sb + (u32)(c % 3) * STG_B;

#pragma unroll
        for (int s = 0; s < 4; s++){
            const u32 tA = stg + (u32)((s >> 1) * HTILE_B);
            const u32 tB = tA + 2*HTILE_B;
            const int sl = s & 1;
            const int ach = 2*sl + ((lane >> 4) & 1);
            const int bch = 2*sl + ((lane >> 3) & 1);

            u32 af[4][4], bf[2][4];
#pragma unroll
            for (int mt = 0; mt < 4; mt++) LDSM4(af[mt], tA + swz(arow + mt*16, ach));
#pragma unroll
            for (int bt = 0; bt < 2; bt++) LDSM4(bf[bt], tB + swz(brow + bt*16, bch));
#pragma unroll
            for (int mt = 0; mt < 4; mt++)
#pragma unroll
                for (int nt = 0; nt < 4; nt++)
                    MMAH(acc[mt][nt], af[mt], bf[nt>>1][(nt&1)*2], bf[nt>>1][(nt&1)*2+1]);
        }
    }

    // ---------------- epilogue ----------------
    const int g = lane >> 2, t4 = lane & 3;
    const int row_base = bm*128 + wm*64;

    if (qkv){
        const int which = bn >> 3;
        half* dst = (which == 0) ? o_q : (which == 1) ? o_k : o_v;
        const float* bb = (which == 0) ? b_q : (which == 1) ? b_k : b_v;
        const int col_base = (bn & 7)*128 + wn*32;
#pragma unroll
        for (int mt = 0; mt < 4; mt++)
#pragma unroll
        for (int nt = 0; nt < 4; nt++){
            const int col = col_base + nt*8 + 2*t4;
            const float b0 = bb[col], b1 = bb[col+1];
#pragma unroll
            for (int h = 0; h < 2; h++){
                const int row = row_base + mt*16 + g + h*8;
                __half2 h2 = __floats2half2_rn(acc[mt][nt][h*2+0] + b0,
                                               acc[mt][nt][h*2+1] + b1);
                *(u32*)(dst + (size_t)row*D_ + col) = *(u32*)&h2;
            }
        }
        return;
    }

    float* Cz = C   ? C   + (size_t)bz*sC : (float*)0;
    half* Chz = o_q ? o_q + (size_t)bz*sC : (half*)0;
    const int col_base = bn*128 + wn*32;

#pragma unroll
    for (int mt = 0; mt < 4; mt++)
#pragma unroll
    for (int nt = 0; nt < 4; nt++){
        const int col = col_base + nt*8 + 2*t4;
        float b0 = 0.f, b1 = 0.f;
        if (b_q){ b0 = b_q[col]; b1 = b_q[col+1]; }
#pragma unroll
        for (int h = 0; h < 2; h++){
            const int row = row_base + mt*16 + g + h*8;
            float v0 = acc[mt][nt][h*2+0] * scale + b0;
            float v1 = acc[mt][nt][h*2+1] * scale + b1;
            if (gelu){
                v0 = 0.5f*v0*(1.0f + erff(v0*0.70710678118654752f));
                v1 = 0.5f*v1*(1.0f + erff(v1*0.70710678118654752f));
            }
            const size_t off = (size_t)row*N + col;
            if (Cz) *(float2*)(Cz + off) = make_float2(v0, v1);
            if (Chz){
                __half2 h2 = __floats2half2_rn(v0, v1);
                *(u32*)(Chz + off) = *(u32*)&h2;
            }
        }
    }
}

// ---------------- fp32 -> fp16 ----------------
__global__ __launch_bounds__(256) void convert_half(
    const float* __restrict__ src, half* __restrict__ dst)
{
    size_t i = (size_t)blockIdx.x * 256 + threadIdx.x;
    float4 f = ((const float4*)src)[i];
    __half2 a = __floats2half2_rn(f.x, f.y);
    __half2 b = __floats2half2_rn(f.z, f.w);
    ((uint2*)dst)[i] = make_uint2(*(u32*)&a, *(u32*)&b);
}

// ---------------- V transpose fp16: vt[b][d][s] = v[b][s][d] ----------------
__global__ __launch_bounds__(256) void transpose_half(
    const half* __restrict__ V, half* __restrict__ VT)
{
    __shared__ half t[32][33];
    const int b = blockIdx.z;
    const int s0 = blockIdx.x*32, d0 = blockIdx.y*32;
    const int tx = threadIdx.x, ty = threadIdx.y;
#pragma unroll
    for (int i = ty; i < 32; i += 8)
        t[i][tx] = V[(size_t)b*S_*D_ + (size_t)(s0+i)*D_ + d0 + tx];
    __syncthreads();
#pragma unroll
    for (int i = ty; i < 32; i += 8)
        VT[(size_t)b*D_*S_ + (size_t)(d0+i)*S_ + s0 + tx] = t[tx][i];
}

// ---------------- causal softmax, warp-per-row, fp16 in-place ----------------
// 8 warps/block, one row each; shuffle reductions, half2 vector I/O.
// Same fp32 max/exp/sum math as before -> numerically identical output.
__global__ __launch_bounds__(256) void softmax_warp(half* __restrict__ SC)
{
    const int r = blockIdx.x * 8 + (threadIdx.x >> 5);  // global row 0..16383
    const int b = r >> 11;          // /S_
    const int q = r & (S_ - 1);
    const int lane = threadIdx.x & 31;
    half* row = SC + ((size_t)b*S_ + q)*S_;
    const int n = q + 1;                       // valid entries
    const int nceil = ((q >> 7) + 1) << 7;     // 128-multiple (PV K bound)
    const int nv = nceil >> 1;                 // half2 count

    // pass 1: row max over [0, n)
    float m = -INFINITY;
    for (int i = lane; i < nv; i += 32){
        __half2 h2 = ((const __half2*)row)[i];
        float v0 = __low2float(h2), v1 = __high2float(h2);
        int e = i*2;
        if (e   < n) m = fmaxf(m, v0);
        if (e+1 < n) m = fmaxf(m, v1);
    }
#pragma unroll
    for (int s = 16; s > 0; s >>= 1) m = fmaxf(m, __shfl_xor_sync(0xFFFFFFFFu, m, s));

    // pass 2: exp + sum (row stays L1-hot; ~4KB/warp)
    float sum = 0.f;
    for (int i = lane; i < nv; i += 32){
        __half2 h2 = ((const __half2*)row)[i];
        int e = i*2;
        float e0 = (e   < n) ? __expf(__low2float(h2)  - m) : 0.f;
        float e1 = (e+1 < n) ? __expf(__high2float(h2) - m) : 0.f;
        sum += e0 + e1;
    }
#pragma unroll
    for (int s = 16; s > 0; s >>= 1) sum += __shfl_xor_sync(0xFFFFFFFFu, sum, s);
    const float inv = 1.0f / sum;

    // pass 3: write normalized probs, zero the padded tail
    for (int i = lane; i < nv; i += 32){
        __half2 h2 = ((const __half2*)row)[i];
        int e = i*2;
        float p0 = (e   < n) ? __expf(__low2float(h2)  - m) * inv : 0.f;
        float p1 = (e+1 < n) ? __expf(__high2float(h2) - m) * inv : 0.f;
        ((__half2*)row)[i] = __floats2half2_rn(p0, p1);
    }
}

// ---------------- launch ----------------
extern "C" void kernel_launch(void* const* d_in, const int* in_sizes, int n_in,
                              void* d_out, int out_size)
{
    const float* x  = (const float*)d_in[0];
    const float* Wq = (const float*)d_in[1];
    const float* bq = (const float*)d_in[2];
    const float* Wk = (const float*)d_in[3];
    const float* bk = (const float*)d_in[4];
    const float* Wv = (const float*)d_in[5];
    const float* bv = (const float*)d_in[6];
    const float* W1 = (const float*)d_in[7];
    const float* b1 = (const float*)d_in[8];
    const float* W2 = (const float*)d_in[9];
    const float* b2 = (const float*)d_in[10];
    float* out = (float*)d_out;

    half *xf,*Wqkv,*W1f,*W2f,*qf,*kf,*vf,*vtf,*scf,*aof,*hf;
    cudaGetSymbolAddress((void**)&xf,  g_xf);
    cudaGetSymbolAddress((void**)&Wqkv,g_Wqkv);
    cudaGetSymbolAddress((void**)&W1f, g_W1f);
    cudaGetSymbolAddress((void**)&W2f, g_W2f);
    cudaGetSymbolAddress((void**)&qf,  g_qf);
    cudaGetSymbolAddress((void**)&kf,  g_kf);
    cudaGetSymbolAddress((void**)&vf,  g_vf);
    cudaGetSymbolAddress((void**)&vtf, g_vtf);
    cudaGetSymbolAddress((void**)&scf, g_scf);
    cudaGetSymbolAddress((void**)&aof, g_aof);
    cudaGetSymbolAddress((void**)&hf,  g_hf);

    cudaFuncSetAttribute(gemm_fp16, cudaFuncAttributeMaxDynamicSharedMemorySize, SMEM_SZ);

    // launches 0-4: converts — launch #5 = fused QKV GEMM (ncu -s 5 -c 1 lands there)
    convert_half<<<(size_t)M_*D_/1024, 256>>>(x,  xf);
    convert_half<<<(size_t)D_*D_/1024, 256>>>(Wq, Wqkv);
    convert_half<<<(size_t)D_*D_/1024, 256>>>(Wk, Wqkv + (size_t)D_*D_);
    convert_half<<<(size_t)D_*D_/1024, 256>>>(Wv, Wqkv + (size_t)2*D_*D_);
    convert_half<<<(size_t)DFF_*D_/1024, 256>>>(W1, W1f);

    // fused QKV projection: [16384 x 1024] @ [3072 x 1024]^T, epilogue routes q/k/v
    gemm_fp16<<<dim3(3*D_/128, M_/128, 1), 256, SMEM_SZ>>>(
        xf, Wqkv, bq, bk, bv, (float*)0, qf, kf, vf,
        3*D_, D_, 0,0,0, 1.f, 0, 0, 1);

    transpose_half<<<dim3(S_/32, D_/32, B_), dim3(32, 8)>>>(vf, vtf);

    // scores = (1/32) q k^T -> fp16 scf (causal block skip)
    gemm_fp16<<<dim3(S_/128, S_/128, B_), 256, SMEM_SZ>>>(
        qf, kf, (float*)0, (float*)0, (float*)0, (float*)0, scf, (half*)0, (half*)0,
        S_, D_, (long)S_*D_, (long)S_*D_, (long)S_*S_, 0.03125f, 0, 1, 0);

    softmax_warp<<<M_/8, 256>>>(scf);

    // attn = P @ vt^T (K bounded at diagonal, longest blocks first)
    gemm_fp16<<<dim3(D_/128, S_/128, B_), 256, SMEM_SZ>>>(
        scf, vtf, (float*)0, (float*)0, (float*)0, (float*)0, aof, (half*)0, (half*)0,
        D_, S_, (long)S_*S_, (long)D_*S_, (long)S_*D_, 1.f, 0, 2, 0);

    // MLP
    gemm_fp16<<<dim3(DFF_/128, M_/128, 1), 256, SMEM_SZ>>>(
        aof, W1f, b1, (float*)0, (float*)0, (float*)0, hf, (half*)0, (half*)0,
        DFF_, D_, 0,0,0, 1.f, 1, 0, 0);
    convert_half<<<(size_t)D_*DFF_/1024, 256>>>(W2, W2f);
    gemm_fp16<<<dim3(D_/128, M_/128, 1), 256, SMEM_SZ>>>(
        hf, W2f, b2, (float*)0, (float*)0, out, (half*)0, (half*)0, (half*)0,
        D_, DFF_, 0,0,0, 1.f, 0, 0, 0);
}